// round 2
// baseline (speedup 1.0000x reference)
#include <cuda_runtime.h>

// Problem dims (fixed by the reference)
#define T_TOK  5888   // N*46 tokens
#define C_DIM  512
#define CI_DIM 256
#define NUMB   46
#define NBATCH 128

// Scratch (allocation-free rule: __device__ globals)
__device__ float g_feat[T_TOK * C_DIM];   // 12.06 MB
__device__ float g_xt[T_TOK * CI_DIM];    // 6.03 MB
__device__ float g_xp[T_TOK * CI_DIM];
__device__ float g_gx[T_TOK * CI_DIM];
__device__ float g_y [T_TOK * CI_DIM];

// ---------------------------------------------------------------------------
// BN (inference) + ReLU + transpose (N,C,46) -> feat (T, C)
// ---------------------------------------------------------------------------
__global__ void __launch_bounds__(256)
bn_relu_kernel(const float* __restrict__ ori,
               const float* __restrict__ gamma,
               const float* __restrict__ beta,
               const float* __restrict__ mean,
               const float* __restrict__ var)
{
    int idx = blockIdx.x * blockDim.x + threadIdx.x;
    if (idx >= T_TOK * C_DIM) return;
    int i = idx / C_DIM;          // token index (n*46 + t)
    int c = idx - i * C_DIM;
    int n = i / NUMB;
    int t = i - n * NUMB;
    float inv = gamma[c] * rsqrtf(var[c] + 1e-5f);
    float b   = beta[c] - mean[c] * inv;
    float v   = ori[(n * C_DIM + c) * NUMB + t] * inv + b;
    g_feat[idx] = fmaxf(v, 0.f);
}

// ---------------------------------------------------------------------------
// NT SGEMM: C[M,N] = A[M,K] @ B[N,K]^T (+ bias[N]) (+ mask) (+ final epilogue)
// 64x64 tile, BK=32, 256 threads, 4x4 per thread. All dims multiples of 64/32.
// ---------------------------------------------------------------------------
template<bool MASK, bool FINAL>
__global__ void __launch_bounds__(256)
gemm_nt_kernel(const float* __restrict__ A,
               const float* __restrict__ B,
               const float* __restrict__ bias,
               float* __restrict__ Cout,
               int M, int N, int K,
               const float* __restrict__ ori)
{
    __shared__ float As[32][64];
    __shared__ float Bs[32][64];

    const int bm = blockIdx.y * 64;
    const int bn = blockIdx.x * 64;
    const int tid = threadIdx.x;
    const int tx = tid & 15;          // column group (N)
    const int ty = tid >> 4;          // row group (M)

    float acc[4][4];
#pragma unroll
    for (int i = 0; i < 4; i++)
#pragma unroll
        for (int j = 0; j < 4; j++) acc[i][j] = 0.f;

    const int lr = tid >> 3;          // 0..31
    const int lc = (tid & 7) << 2;    // 0,4,...,28

    for (int kk = 0; kk < K; kk += 32) {
#pragma unroll
        for (int l = 0; l < 2; l++) {
            int r = lr + l * 32;
            float4 va = *(const float4*)(A + (size_t)(bm + r) * K + kk + lc);
            As[lc + 0][r] = va.x; As[lc + 1][r] = va.y;
            As[lc + 2][r] = va.z; As[lc + 3][r] = va.w;
            float4 vb = *(const float4*)(B + (size_t)(bn + r) * K + kk + lc);
            Bs[lc + 0][r] = vb.x; Bs[lc + 1][r] = vb.y;
            Bs[lc + 2][r] = vb.z; Bs[lc + 3][r] = vb.w;
        }
        __syncthreads();
#pragma unroll
        for (int k = 0; k < 32; k++) {
            float4 a = *(const float4*)&As[k][ty << 2];
            float4 b = *(const float4*)&Bs[k][tx << 2];
            acc[0][0] += a.x * b.x; acc[0][1] += a.x * b.y;
            acc[0][2] += a.x * b.z; acc[0][3] += a.x * b.w;
            acc[1][0] += a.y * b.x; acc[1][1] += a.y * b.y;
            acc[1][2] += a.y * b.z; acc[1][3] += a.y * b.w;
            acc[2][0] += a.z * b.x; acc[2][1] += a.z * b.y;
            acc[2][2] += a.z * b.z; acc[2][3] += a.z * b.w;
            acc[3][0] += a.w * b.x; acc[3][1] += a.w * b.y;
            acc[3][2] += a.w * b.z; acc[3][3] += a.w * b.w;
        }
        __syncthreads();
    }

    float bv[4] = {0.f, 0.f, 0.f, 0.f};
    if (bias) {
#pragma unroll
        for (int j = 0; j < 4; j++) bv[j] = bias[bn + (tx << 2) + j];
    }
#pragma unroll
    for (int i = 0; i < 4; i++) {
        int row = bm + (ty << 2) + i;
#pragma unroll
        for (int j = 0; j < 4; j++) {
            int col = bn + (tx << 2) + j;
            float v = acc[i][j] + bv[j];
            if (MASK) {
                if (row / NUMB == col / NUMB) v = -1000.0f;
            }
            if (FINAL) {
                int n = row / NUMB, t = row - n * NUMB;
                v += ori[(n * C_DIM + col) * NUMB + t];
            }
            Cout[(size_t)row * N + col] = v;
        }
    }
}

// ---------------------------------------------------------------------------
// NN SGEMM: C[M,N] = A[M,K] @ B[K,N]   (y = softmax @ g_x)
// ---------------------------------------------------------------------------
__global__ void __launch_bounds__(256)
gemm_nn_kernel(const float* __restrict__ A,
               const float* __restrict__ B,
               float* __restrict__ Cout,
               int M, int N, int K)
{
    __shared__ float As[32][64];
    __shared__ float Bs[32][64];

    const int bm = blockIdx.y * 64;
    const int bn = blockIdx.x * 64;
    const int tid = threadIdx.x;
    const int tx = tid & 15;
    const int ty = tid >> 4;

    float acc[4][4];
#pragma unroll
    for (int i = 0; i < 4; i++)
#pragma unroll
        for (int j = 0; j < 4; j++) acc[i][j] = 0.f;

    const int lr = tid >> 3;          // A: 0..31
    const int lc = (tid & 7) << 2;
    const int br = tid >> 4;          // B: 0..15
    const int bc = (tid & 15) << 2;

    for (int kk = 0; kk < K; kk += 32) {
#pragma unroll
        for (int l = 0; l < 2; l++) {
            int r = lr + l * 32;
            float4 va = *(const float4*)(A + (size_t)(bm + r) * K + kk + lc);
            As[lc + 0][r] = va.x; As[lc + 1][r] = va.y;
            As[lc + 2][r] = va.z; As[lc + 3][r] = va.w;
            int rb = br + l * 16;
            float4 vb = *(const float4*)(B + (size_t)(kk + rb) * N + bn + bc);
            *(float4*)&Bs[rb][bc] = vb;
        }
        __syncthreads();
#pragma unroll
        for (int k = 0; k < 32; k++) {
            float4 a = *(const float4*)&As[k][ty << 2];
            float4 b = *(const float4*)&Bs[k][tx << 2];
            acc[0][0] += a.x * b.x; acc[0][1] += a.x * b.y;
            acc[0][2] += a.x * b.z; acc[0][3] += a.x * b.w;
            acc[1][0] += a.y * b.x; acc[1][1] += a.y * b.y;
            acc[1][2] += a.y * b.z; acc[1][3] += a.y * b.w;
            acc[2][0] += a.z * b.x; acc[2][1] += a.z * b.y;
            acc[2][2] += a.z * b.z; acc[2][3] += a.z * b.w;
            acc[3][0] += a.w * b.x; acc[3][1] += a.w * b.y;
            acc[3][2] += a.w * b.z; acc[3][3] += a.w * b.w;
        }
        __syncthreads();
    }
#pragma unroll
    for (int i = 0; i < 4; i++) {
        int row = bm + (ty << 2) + i;
#pragma unroll
        for (int j = 0; j < 4; j++) {
            int col = bn + (tx << 2) + j;
            Cout[(size_t)row * N + col] = acc[i][j];
        }
    }
}

// ---------------------------------------------------------------------------
// Row softmax in place. One block per row; 256 threads x 23 elems = 5888.
// ---------------------------------------------------------------------------
__global__ void __launch_bounds__(256)
softmax_kernel(float* __restrict__ attn)
{
    const int row = blockIdx.x;
    float* p = attn + (size_t)row * T_TOK;
    const int tid = threadIdx.x;
    const unsigned FULL = 0xffffffffu;
    __shared__ float red[8];

    float v[23];
    float mx = -1e30f;
#pragma unroll
    for (int i = 0; i < 23; i++) {
        v[i] = p[tid + (i << 8)];
        mx = fmaxf(mx, v[i]);
    }
#pragma unroll
    for (int o = 16; o; o >>= 1) mx = fmaxf(mx, __shfl_xor_sync(FULL, mx, o));
    if ((tid & 31) == 0) red[tid >> 5] = mx;
    __syncthreads();
    if (tid < 32) {
        float m2 = (tid < 8) ? red[tid] : -1e30f;
#pragma unroll
        for (int o = 4; o; o >>= 1) m2 = fmaxf(m2, __shfl_xor_sync(FULL, m2, o));
        if (tid == 0) red[0] = m2;
    }
    __syncthreads();
    mx = red[0];
    __syncthreads();

    float s = 0.f;
#pragma unroll
    for (int i = 0; i < 23; i++) {
        v[i] = __expf(v[i] - mx);
        s += v[i];
    }
#pragma unroll
    for (int o = 16; o; o >>= 1) s += __shfl_xor_sync(FULL, s, o);
    if ((tid & 31) == 0) red[tid >> 5] = s;
    __syncthreads();
    if (tid < 32) {
        float s2 = (tid < 8) ? red[tid] : 0.f;
#pragma unroll
        for (int o = 4; o; o >>= 1) s2 += __shfl_xor_sync(FULL, s2, o);
        if (tid == 0) red[0] = s2;
    }
    __syncthreads();
    float inv = 1.f / red[0];
#pragma unroll
    for (int i = 0; i < 23; i++) p[tid + (i << 8)] = v[i] * inv;
}

// ---------------------------------------------------------------------------
extern "C" void kernel_launch(void* const* d_in, const int* in_sizes, int n_in,
                              void* d_out, int out_size)
{
    const float* ori     = (const float*)d_in[0];
    const float* gamma   = (const float*)d_in[1];
    const float* beta    = (const float*)d_in[2];
    const float* mean    = (const float*)d_in[3];
    const float* var     = (const float*)d_in[4];
    const float* theta_w = (const float*)d_in[5];
    const float* theta_b = (const float*)d_in[6];
    const float* phi_w   = (const float*)d_in[7];
    const float* phi_b   = (const float*)d_in[8];
    const float* g_w     = (const float*)d_in[9];
    const float* g_b     = (const float*)d_in[10];
    const float* W_w     = (const float*)d_in[11];
    const float* W_b     = (const float*)d_in[12];

    float* att_fea = (float*)d_out;                                   // (128,46,512)
    float* fdiv    = (float*)d_out + (size_t)NBATCH * NUMB * C_DIM;   // (5888,5888)

    float *feat, *xt, *xp, *gx, *y;
    cudaGetSymbolAddress((void**)&feat, g_feat);
    cudaGetSymbolAddress((void**)&xt,   g_xt);
    cudaGetSymbolAddress((void**)&xp,   g_xp);
    cudaGetSymbolAddress((void**)&gx,   g_gx);
    cudaGetSymbolAddress((void**)&y,    g_y);

    // 1) BN + ReLU + transpose -> feat (T, C)
    bn_relu_kernel<<<(T_TOK * C_DIM + 255) / 256, 256>>>(ori, gamma, beta, mean, var);

    // 2) Projections: x_theta / x_phi / g_x  (T,512)@(512,256)^T + bias
    dim3 gproj(CI_DIM / 64, T_TOK / 64);
    gemm_nt_kernel<false, false><<<gproj, 256>>>(feat, theta_w, theta_b, xt,
                                                 T_TOK, CI_DIM, C_DIM, nullptr);
    gemm_nt_kernel<false, false><<<gproj, 256>>>(feat, phi_w, phi_b, xp,
                                                 T_TOK, CI_DIM, C_DIM, nullptr);
    gemm_nt_kernel<false, false><<<gproj, 256>>>(feat, g_w, g_b, gx,
                                                 T_TOK, CI_DIM, C_DIM, nullptr);

    // 3) attn = x_theta @ x_phi^T with block-diagonal mask -> logits in fdiv
    dim3 gattn(T_TOK / 64, T_TOK / 64);
    gemm_nt_kernel<true, false><<<gattn, 256>>>(xt, xp, nullptr, fdiv,
                                                T_TOK, T_TOK, CI_DIM, nullptr);

    // 4) softmax rows, in place (this IS the f_div_C output)
    softmax_kernel<<<T_TOK, 256>>>(fdiv);

    // 5) y = f_div_C @ g_x   (5888,5888)@(5888,256)
    dim3 gy(CI_DIM / 64, T_TOK / 64);
    gemm_nn_kernel<<<gy, 256>>>(fdiv, gx, y, T_TOK, CI_DIM, T_TOK);

    // 6) att_fea = y @ W_w^T + W_b + ori^T
    dim3 gfin(C_DIM / 64, T_TOK / 64);
    gemm_nt_kernel<false, true><<<gfin, 256>>>(y, W_w, W_b, att_fea,
                                               T_TOK, C_DIM, CI_DIM, ori);
}

// round 4
// speedup vs baseline: 1.8124x; 1.8124x over previous
#include <cuda_runtime.h>

#define T_TOK 5888
#define NUMB  46
#define NB    128

// Scratch (__device__ globals; no allocation allowed)
__device__ float g_feat[T_TOK * 512];        // BN+ReLU features (T, 512)
__device__ float g_xall[T_TOK * 768];        // [xt | xp | gx] (T, 768)
__device__ float g_yp[4][T_TOK * 256];       // split-K partials for y
__device__ float g_y[T_TOK * 256];           // y (T, 256)

typedef unsigned long long ull;

__device__ __forceinline__ ull pack2(float lo, float hi) {
    ull r; asm("mov.b64 %0,{%1,%2};" : "=l"(r) : "f"(lo), "f"(hi)); return r;
}
__device__ __forceinline__ void unpack2(ull v, float& lo, float& hi) {
    asm("mov.b64 {%0,%1},%2;" : "=f"(lo), "=f"(hi) : "l"(v));
}
__device__ __forceinline__ void ffma2(ull& acc, ull a, ull b) {
    asm("fma.rn.f32x2 %0,%1,%2,%0;" : "+l"(acc) : "l"(a), "l"(b));
}

// ---------------------------------------------------------------------------
// BN(inference)+ReLU+transpose: ori (N,C,46) -> feat (T=N*46, C) via smem tile
// ---------------------------------------------------------------------------
__global__ void __launch_bounds__(256)
bn_relu_kernel(const float* __restrict__ ori,
               const float* __restrict__ gamma,
               const float* __restrict__ beta,
               const float* __restrict__ mean,
               const float* __restrict__ var)
{
    __shared__ float s[32][47];
    const int n  = blockIdx.y;
    const int c0 = blockIdx.x * 32;
    const int tid = threadIdx.x;

    for (int i = tid; i < 32 * NUMB; i += 256) {
        int c = i / NUMB;
        int t = i - c * NUMB;
        int cc = c0 + c;
        float inv = gamma[cc] * rsqrtf(var[cc] + 1e-5f);
        float b   = beta[cc] - mean[cc] * inv;
        float v   = ori[(size_t)(n * 512 + cc) * NUMB + t] * inv + b;
        s[c][t] = fmaxf(v, 0.f);
    }
    __syncthreads();
    for (int i = tid; i < 32 * NUMB; i += 256) {
        int t = i >> 5;
        int c = i & 31;
        g_feat[(size_t)(n * NUMB + t) * 512 + c0 + c] = s[c][t];
    }
}

// ---------------------------------------------------------------------------
// NT SGEMM 128x128x16, 256 thr, 8x8/thread via packed f32x2 FMA, dbl-buffered.
// MODE 0: fused projections (z selects weight/bias, output col offset z*256)
// MODE 1: attention logits with block-diagonal mask
// MODE 2: final projection: bias + residual from ori
// ---------------------------------------------------------------------------
template<int MODE>
__global__ void __launch_bounds__(256, 2)
gemm_nt(const float* __restrict__ A,
        const float* __restrict__ B0, const float* __restrict__ B1,
        const float* __restrict__ B2,
        const float* __restrict__ bias0, const float* __restrict__ bias1,
        const float* __restrict__ bias2,
        float* __restrict__ Cout,
        int lda, int ldb, int ldc, int K,
        const float* __restrict__ ori)
{
    __shared__ float As[2][16][128];
    __shared__ float Bs[2][16][128];

    const int bm = blockIdx.y * 128;
    const int bn = blockIdx.x * 128;

    const float* B = B0;
    const float* bias = bias0;
    float* C = Cout;
    if (MODE == 0) {
        int z = blockIdx.z;
        B    = (z == 0) ? B0 : (z == 1) ? B1 : B2;
        bias = (z == 0) ? bias0 : (z == 1) ? bias1 : bias2;
        C    = Cout + z * 256;
    }

    const int tid  = threadIdx.x;
    const int tx   = tid & 15;
    const int ty   = tid >> 4;
    const int lrow = tid >> 2;          // 0..63
    const int lcol = (tid & 3) << 2;    // 0,4,8,12

    ull acc[8][4];
#pragma unroll
    for (int i = 0; i < 8; i++)
#pragma unroll
        for (int j = 0; j < 4; j++) acc[i][j] = 0ull;

    const float* Aptr = A + (size_t)(bm + lrow) * lda + lcol;
    const float* Bptr = B + (size_t)(bn + lrow) * ldb + lcol;

    // preload tile 0
    {
        float4 a0 = *(const float4*)Aptr;
        float4 a1 = *(const float4*)(Aptr + (size_t)64 * lda);
        float4 b0 = *(const float4*)Bptr;
        float4 b1 = *(const float4*)(Bptr + (size_t)64 * ldb);
        As[0][lcol+0][lrow]    = a0.x; As[0][lcol+1][lrow]    = a0.y;
        As[0][lcol+2][lrow]    = a0.z; As[0][lcol+3][lrow]    = a0.w;
        As[0][lcol+0][lrow+64] = a1.x; As[0][lcol+1][lrow+64] = a1.y;
        As[0][lcol+2][lrow+64] = a1.z; As[0][lcol+3][lrow+64] = a1.w;
        Bs[0][lcol+0][lrow]    = b0.x; Bs[0][lcol+1][lrow]    = b0.y;
        Bs[0][lcol+2][lrow]    = b0.z; Bs[0][lcol+3][lrow]    = b0.w;
        Bs[0][lcol+0][lrow+64] = b1.x; Bs[0][lcol+1][lrow+64] = b1.y;
        Bs[0][lcol+2][lrow+64] = b1.z; Bs[0][lcol+3][lrow+64] = b1.w;
    }
    __syncthreads();

    const int ntile = K >> 4;
    int buf = 0;
    for (int t = 0; t < ntile; t++) {
        float4 a0n, a1n, b0n, b1n;
        if (t + 1 < ntile) {
            const float* Ap = Aptr + (t + 1) * 16;
            const float* Bp = Bptr + (t + 1) * 16;
            a0n = *(const float4*)Ap;
            a1n = *(const float4*)(Ap + (size_t)64 * lda);
            b0n = *(const float4*)Bp;
            b1n = *(const float4*)(Bp + (size_t)64 * ldb);
        }
#pragma unroll
        for (int k = 0; k < 16; k++) {
            float4 av0 = *(const float4*)&As[buf][k][ty << 2];
            float4 av1 = *(const float4*)&As[buf][k][(ty << 2) + 64];
            const ull* bp0 = (const ull*)&Bs[buf][k][tx << 2];
            const ull* bp1 = (const ull*)&Bs[buf][k][(tx << 2) + 64];
            ull b01 = bp0[0], b23 = bp0[1];
            ull b45 = bp1[0], b67 = bp1[1];
            float a[8] = {av0.x, av0.y, av0.z, av0.w,
                          av1.x, av1.y, av1.z, av1.w};
#pragma unroll
            for (int i = 0; i < 8; i++) {
                ull ap = pack2(a[i], a[i]);
                ffma2(acc[i][0], ap, b01);
                ffma2(acc[i][1], ap, b23);
                ffma2(acc[i][2], ap, b45);
                ffma2(acc[i][3], ap, b67);
            }
        }
        if (t + 1 < ntile) {
            int nb = buf ^ 1;
            As[nb][lcol+0][lrow]    = a0n.x; As[nb][lcol+1][lrow]    = a0n.y;
            As[nb][lcol+2][lrow]    = a0n.z; As[nb][lcol+3][lrow]    = a0n.w;
            As[nb][lcol+0][lrow+64] = a1n.x; As[nb][lcol+1][lrow+64] = a1n.y;
            As[nb][lcol+2][lrow+64] = a1n.z; As[nb][lcol+3][lrow+64] = a1n.w;
            Bs[nb][lcol+0][lrow]    = b0n.x; Bs[nb][lcol+1][lrow]    = b0n.y;
            Bs[nb][lcol+2][lrow]    = b0n.z; Bs[nb][lcol+3][lrow]    = b0n.w;
            Bs[nb][lcol+0][lrow+64] = b1n.x; Bs[nb][lcol+1][lrow+64] = b1n.y;
            Bs[nb][lcol+2][lrow+64] = b1n.z; Bs[nb][lcol+3][lrow+64] = b1n.w;
            __syncthreads();
            buf = nb;
        }
    }

    // epilogue
    float bv[8];
#pragma unroll
    for (int j = 0; j < 8; j++) {
        int col = (j < 4) ? (tx << 2) + j : 64 + (tx << 2) + (j - 4);
        bv[j] = (MODE == 0 || MODE == 2) ? bias[bn + col] : 0.f;
    }
#pragma unroll
    for (int i = 0; i < 8; i++) {
        int row = bm + ((i < 4) ? (ty << 2) + i : 64 + (ty << 2) + (i - 4));
#pragma unroll
        for (int j2 = 0; j2 < 4; j2++) {
            float v0, v1;
            unpack2(acc[i][j2], v0, v1);
            int j = j2 * 2;
            int col0 = bn + ((j < 4) ? (tx << 2) + j : 64 + (tx << 2) + (j - 4));
            v0 += bv[j];
            v1 += bv[j + 1];
            if (MODE == 1) {
                int rb = row / NUMB;
                if (rb == col0 / NUMB)       v0 = -1000.0f;
                if (rb == (col0 + 1) / NUMB) v1 = -1000.0f;
            }
            if (MODE == 2) {
                int n = row / NUMB, t = row - n * NUMB;
                v0 += ori[(size_t)(n * 512 + col0) * NUMB + t];
                v1 += ori[(size_t)(n * 512 + col0 + 1) * NUMB + t];
            }
            float2 st = make_float2(v0, v1);
            *(float2*)&C[(size_t)row * ldc + col0] = st;
        }
    }
}

// ---------------------------------------------------------------------------
// NN SGEMM split-K: yp[z] = fdiv[:, z*1472:(z+1)*1472] @ gx[chunk]  (128x128)
// ---------------------------------------------------------------------------
__global__ void __launch_bounds__(256, 2)
gemm_nn_splitk(const float* __restrict__ A,   // fdiv (T, T)
               const float* __restrict__ B,   // gx  (T, 256) inside xall (ldb)
               int lda, int ldb, int Kchunk)
{
    __shared__ float As[2][16][128];
    __shared__ float Bs[2][16][128];

    const int bm = blockIdx.y * 128;
    const int bn = blockIdx.x * 128;
    const int z  = blockIdx.z;
    const int k0 = z * Kchunk;
    float* C = g_yp[z];

    const int tid  = threadIdx.x;
    const int tx   = tid & 15;
    const int ty   = tid >> 4;
    const int lrow = tid >> 2;          // A: 0..63
    const int lcol = (tid & 3) << 2;
    const int brow = tid >> 4;          // B: 0..15
    const int bcol = (tid & 15) << 2;   // 0..60

    ull acc[8][4];
#pragma unroll
    for (int i = 0; i < 8; i++)
#pragma unroll
        for (int j = 0; j < 4; j++) acc[i][j] = 0ull;

    const float* Aptr = A + (size_t)(bm + lrow) * lda + k0 + lcol;
    const float* Bptr = B + (size_t)(k0 + brow) * ldb + bn + bcol;

    {
        float4 a0 = *(const float4*)Aptr;
        float4 a1 = *(const float4*)(Aptr + (size_t)64 * lda);
        float4 b0 = *(const float4*)Bptr;
        float4 b1 = *(const float4*)(Bptr + 64);
        As[0][lcol+0][lrow]    = a0.x; As[0][lcol+1][lrow]    = a0.y;
        As[0][lcol+2][lrow]    = a0.z; As[0][lcol+3][lrow]    = a0.w;
        As[0][lcol+0][lrow+64] = a1.x; As[0][lcol+1][lrow+64] = a1.y;
        As[0][lcol+2][lrow+64] = a1.z; As[0][lcol+3][lrow+64] = a1.w;
        *(float4*)&Bs[0][brow][bcol]      = b0;
        *(float4*)&Bs[0][brow][bcol + 64] = b1;
    }
    __syncthreads();

    const int ntile = Kchunk >> 4;
    int buf = 0;
    for (int t = 0; t < ntile; t++) {
        float4 a0n, a1n, b0n, b1n;
        if (t + 1 < ntile) {
            const float* Ap = Aptr + (t + 1) * 16;
            const float* Bp = Bptr + (size_t)(t + 1) * 16 * ldb;
            a0n = *(const float4*)Ap;
            a1n = *(const float4*)(Ap + (size_t)64 * lda);
            b0n = *(const float4*)Bp;
            b1n = *(const float4*)(Bp + 64);
        }
#pragma unroll
        for (int k = 0; k < 16; k++) {
            float4 av0 = *(const float4*)&As[buf][k][ty << 2];
            float4 av1 = *(const float4*)&As[buf][k][(ty << 2) + 64];
            const ull* bp0 = (const ull*)&Bs[buf][k][tx << 2];
            const ull* bp1 = (const ull*)&Bs[buf][k][(tx << 2) + 64];
            ull b01 = bp0[0], b23 = bp0[1];
            ull b45 = bp1[0], b67 = bp1[1];
            float a[8] = {av0.x, av0.y, av0.z, av0.w,
                          av1.x, av1.y, av1.z, av1.w};
#pragma unroll
            for (int i = 0; i < 8; i++) {
                ull ap = pack2(a[i], a[i]);
                ffma2(acc[i][0], ap, b01);
                ffma2(acc[i][1], ap, b23);
                ffma2(acc[i][2], ap, b45);
                ffma2(acc[i][3], ap, b67);
            }
        }
        if (t + 1 < ntile) {
            int nb = buf ^ 1;
            As[nb][lcol+0][lrow]    = a0n.x; As[nb][lcol+1][lrow]    = a0n.y;
            As[nb][lcol+2][lrow]    = a0n.z; As[nb][lcol+3][lrow]    = a0n.w;
            As[nb][lcol+0][lrow+64] = a1n.x; As[nb][lcol+1][lrow+64] = a1n.y;
            As[nb][lcol+2][lrow+64] = a1n.z; As[nb][lcol+3][lrow+64] = a1n.w;
            *(float4*)&Bs[nb][brow][bcol]      = b0n;
            *(float4*)&Bs[nb][brow][bcol + 64] = b1n;
            __syncthreads();
            buf = nb;
        }
    }

#pragma unroll
    for (int i = 0; i < 8; i++) {
        int row = bm + ((i < 4) ? (ty << 2) + i : 64 + (ty << 2) + (i - 4));
#pragma unroll
        for (int j2 = 0; j2 < 4; j2++) {
            float v0, v1;
            unpack2(acc[i][j2], v0, v1);
            int j = j2 * 2;
            int col0 = bn + ((j < 4) ? (tx << 2) + j : 64 + (tx << 2) + (j - 4));
            *(float2*)&C[(size_t)row * 256 + col0] = make_float2(v0, v1);
        }
    }
}

// Reduce the 4 split-K partials into g_y (float4 per thread)
__global__ void __launch_bounds__(256)
reduce_y_kernel()
{
    int i = blockIdx.x * 256 + threadIdx.x;   // float4 index
    float4 a = ((const float4*)g_yp[0])[i];
    float4 b = ((const float4*)g_yp[1])[i];
    float4 c = ((const float4*)g_yp[2])[i];
    float4 d = ((const float4*)g_yp[3])[i];
    float4 r;
    r.x = a.x + b.x + c.x + d.x;
    r.y = a.y + b.y + c.y + d.y;
    r.z = a.z + b.z + c.z + d.z;
    r.w = a.w + b.w + c.w + d.w;
    ((float4*)g_y)[i] = r;
}

// ---------------------------------------------------------------------------
// Row softmax in place. One block per row; 256 threads x 23 elems = 5888.
// ---------------------------------------------------------------------------
__global__ void __launch_bounds__(256)
softmax_kernel(float* __restrict__ attn)
{
    const int row = blockIdx.x;
    float* p = attn + (size_t)row * T_TOK;
    const int tid = threadIdx.x;
    const unsigned FULL = 0xffffffffu;
    __shared__ float red[8];

    float v[23];
    float mx = -1e30f;
#pragma unroll
    for (int i = 0; i < 23; i++) {
        v[i] = p[tid + (i << 8)];
        mx = fmaxf(mx, v[i]);
    }
#pragma unroll
    for (int o = 16; o; o >>= 1) mx = fmaxf(mx, __shfl_xor_sync(FULL, mx, o));
    if ((tid & 31) == 0) red[tid >> 5] = mx;
    __syncthreads();
    if (tid < 32) {
        float m2 = (tid < 8) ? red[tid] : -1e30f;
#pragma unroll
        for (int o = 4; o; o >>= 1) m2 = fmaxf(m2, __shfl_xor_sync(FULL, m2, o));
        if (tid == 0) red[0] = m2;
    }
    __syncthreads();
    mx = red[0];
    __syncthreads();

    float s = 0.f;
#pragma unroll
    for (int i = 0; i < 23; i++) {
        v[i] = __expf(v[i] - mx);
        s += v[i];
    }
#pragma unroll
    for (int o = 16; o; o >>= 1) s += __shfl_xor_sync(FULL, s, o);
    if ((tid & 31) == 0) red[tid >> 5] = s;
    __syncthreads();
    if (tid < 32) {
        float s2 = (tid < 8) ? red[tid] : 0.f;
#pragma unroll
        for (int o = 4; o; o >>= 1) s2 += __shfl_xor_sync(FULL, s2, o);
        if (tid == 0) red[0] = s2;
    }
    __syncthreads();
    float inv = 1.f / red[0];
#pragma unroll
    for (int i = 0; i < 23; i++) p[tid + (i << 8)] = v[i] * inv;
}

// ---------------------------------------------------------------------------
extern "C" void kernel_launch(void* const* d_in, const int* in_sizes, int n_in,
                              void* d_out, int out_size)
{
    const float* ori     = (const float*)d_in[0];
    const float* gamma   = (const float*)d_in[1];
    const float* beta    = (const float*)d_in[2];
    const float* mean    = (const float*)d_in[3];
    const float* var     = (const float*)d_in[4];
    const float* theta_w = (const float*)d_in[5];
    const float* theta_b = (const float*)d_in[6];
    const float* phi_w   = (const float*)d_in[7];
    const float* phi_b   = (const float*)d_in[8];
    const float* g_w     = (const float*)d_in[9];
    const float* g_b     = (const float*)d_in[10];
    const float* W_w     = (const float*)d_in[11];
    const float* W_b     = (const float*)d_in[12];

    float* att_fea = (float*)d_out;                                  // (128,46,512)
    float* fdiv    = (float*)d_out + (size_t)NB * NUMB * 512;        // (5888,5888)

    float *feat, *xall, *y;
    cudaGetSymbolAddress((void**)&feat, g_feat);
    cudaGetSymbolAddress((void**)&xall, g_xall);
    cudaGetSymbolAddress((void**)&y,    g_y);

    // 1) BN + ReLU + transpose -> feat (T, 512)
    bn_relu_kernel<<<dim3(16, NB), 256>>>(ori, gamma, beta, mean, var);

    // 2) Fused projections -> xall = [xt | xp | gx] (T, 768)
    gemm_nt<0><<<dim3(2, 46, 3), 256>>>(feat,
                                        theta_w, phi_w, g_w,
                                        theta_b, phi_b, g_b,
                                        xall, 512, 512, 768, 512, nullptr);

    // 3) attn = xt @ xp^T with block-diagonal mask -> logits into fdiv
    gemm_nt<1><<<dim3(46, 46), 256>>>(xall, xall + 256, nullptr, nullptr,
                                      nullptr, nullptr, nullptr,
                                      fdiv, 768, 768, T_TOK, 256, nullptr);

    // 4) softmax rows in place (this IS the f_div_C output)
    softmax_kernel<<<T_TOK, 256>>>(fdiv);

    // 5) y = f_div_C @ g_x  (split-K x4) + reduce
    gemm_nn_splitk<<<dim3(2, 46, 4), 256>>>(fdiv, xall + 512, T_TOK, 768, 1472);
    reduce_y_kernel<<<(T_TOK * 256 / 4) / 256, 256>>>();

    // 6) att_fea = y @ W_w^T + W_b + ori^T
    gemm_nt<2><<<dim3(4, 46), 256>>>(y, W_w, nullptr, nullptr,
                                     W_b, nullptr, nullptr,
                                     att_fea, 256, 256, 512, 256, ori);
}

// round 7
// speedup vs baseline: 2.9128x; 1.6072x over previous
#include <cuda_runtime.h>
#include <cuda_bf16.h>
#include <cstdint>

#define T_TOK 5888
#define NUMB  46
#define NB    128

// ---------------------------------------------------------------------------
// Scratch (__device__ globals; no allocation allowed)
// ---------------------------------------------------------------------------
__device__ float g_feat[T_TOK * 512];                  // BN+ReLU features (T, 512)
__device__ float g_gx[T_TOK * 256];                    // gx fp32 (pre-transpose)
__device__ float g_y[T_TOK * 256];                     // y (T, 256)
__device__ __nv_bfloat16 g_qh[T_TOK * 256];            // x_theta hi
__device__ __nv_bfloat16 g_ql[T_TOK * 256];            // x_theta lo
__device__ __nv_bfloat16 g_kh[T_TOK * 256];            // x_phi hi
__device__ __nv_bfloat16 g_kl[T_TOK * 256];            // x_phi lo
__device__ __nv_bfloat16 g_gth[256 * T_TOK];           // g_x^T hi (256, T)
__device__ __nv_bfloat16 g_gtl[256 * T_TOK];           // g_x^T lo
__device__ __nv_bfloat16 g_ph[34668544];               // P hi (T, T)
__device__ __nv_bfloat16 g_pl[34668544];               // P lo (T, T)

typedef unsigned long long ull;

// ---------------------------------------------------------------------------
// PTX helpers (all baseline PTX — no sm_103a-gated instructions)
// ---------------------------------------------------------------------------
__device__ __forceinline__ ull pack2(float lo, float hi) {
    ull r; asm("mov.b64 %0,{%1,%2};" : "=l"(r) : "f"(lo), "f"(hi)); return r;
}
__device__ __forceinline__ void unpack2(ull v, float& lo, float& hi) {
    asm("mov.b64 {%0,%1},%2;" : "=f"(lo), "=f"(hi) : "l"(v));
}
__device__ __forceinline__ void ffma2(ull& acc, ull a, ull b) {
    asm("fma.rn.f32x2 %0,%1,%2,%0;" : "+l"(acc) : "l"(a), "l"(b));
}
__device__ __forceinline__ uint32_t smem_u32(const void* p) {
    uint32_t a;
    asm("{ .reg .u64 t; cvta.to.shared.u64 t, %1; cvt.u32.u64 %0, t; }"
        : "=r"(a) : "l"(p));
    return a;
}
__device__ __forceinline__ void cp16(uint32_t s, const void* g) {
    asm volatile("cp.async.cg.shared.global [%0], [%1], 16;" :: "r"(s), "l"(g) : "memory");
}
__device__ __forceinline__ void cp_commit() {
    asm volatile("cp.async.commit_group;" ::: "memory");
}

__device__ __forceinline__ void ldsm4(uint32_t* r, uint32_t addr) {
    asm volatile("ldmatrix.sync.aligned.m8n8.x4.shared.b16 {%0,%1,%2,%3},[%4];"
                 : "=r"(r[0]), "=r"(r[1]), "=r"(r[2]), "=r"(r[3]) : "r"(addr));
}
__device__ __forceinline__ void mma16816(float* c, const uint32_t* a, const uint32_t* b) {
    asm volatile("mma.sync.aligned.m16n8k16.row.col.f32.bf16.bf16.f32 "
                 "{%0,%1,%2,%3},{%4,%5,%6,%7},{%8,%9},{%0,%1,%2,%3};"
                 : "+f"(c[0]), "+f"(c[1]), "+f"(c[2]), "+f"(c[3])
                 : "r"(a[0]), "r"(a[1]), "r"(a[2]), "r"(a[3]),
                   "r"(b[0]), "r"(b[1]));
}

#define SWZ(x) ((x) ^ (((x) >> 3) & 0x70))

__device__ __forceinline__ void split_bf16(float x, __nv_bfloat16& h, __nv_bfloat16& l) {
    h = __float2bfloat16_rn(x);
    l = __float2bfloat16_rn(x - __bfloat162float(h));
}

// ---------------------------------------------------------------------------
// BN(inference)+ReLU+transpose: ori (N,C,46) -> feat (T=N*46, C)
// ---------------------------------------------------------------------------
__global__ void __launch_bounds__(256)
bn_relu_kernel(const float* __restrict__ ori,
               const float* __restrict__ gamma,
               const float* __restrict__ beta,
               const float* __restrict__ mean,
               const float* __restrict__ var)
{
    __shared__ float s[32][47];
    const int n  = blockIdx.y;
    const int c0 = blockIdx.x * 32;
    const int tid = threadIdx.x;

    for (int i = tid; i < 32 * NUMB; i += 256) {
        int c = i / NUMB;
        int t = i - c * NUMB;
        int cc = c0 + c;
        float inv = gamma[cc] * rsqrtf(var[cc] + 1e-5f);
        float b   = beta[cc] - mean[cc] * inv;
        float v   = ori[(size_t)(n * 512 + cc) * NUMB + t] * inv + b;
        s[c][t] = fmaxf(v, 0.f);
    }
    __syncthreads();
    for (int i = tid; i < 32 * NUMB; i += 256) {
        int t = i >> 5;
        int c = i & 31;
        g_feat[(size_t)(n * NUMB + t) * 512 + c0 + c] = s[c][t];
    }
}

// ---------------------------------------------------------------------------
// FFMA2 NT SGEMM 128x128x16. MODE 0: fused projections, epilogue writes bf16
// hi/lo (z<2) or fp32 gx (z==2). MODE 2: final projection + bias + residual.
// ---------------------------------------------------------------------------
template<int MODE>
__global__ void __launch_bounds__(256, 2)
gemm_nt(const float* __restrict__ A,
        const float* __restrict__ B0, const float* __restrict__ B1,
        const float* __restrict__ B2,
        const float* __restrict__ bias0, const float* __restrict__ bias1,
        const float* __restrict__ bias2,
        float* __restrict__ Cout,
        int lda, int ldb, int ldc, int K,
        const float* __restrict__ ori)
{
    __shared__ float As[2][16][128];
    __shared__ float Bs[2][16][128];

    const int bm = blockIdx.y * 128;
    const int bn = blockIdx.x * 128;

    const float* B = B0;
    const float* bias = bias0;
    int z = 0;
    if (MODE == 0) {
        z = blockIdx.z;
        B    = (z == 0) ? B0 : (z == 1) ? B1 : B2;
        bias = (z == 0) ? bias0 : (z == 1) ? bias1 : bias2;
    }

    const int tid  = threadIdx.x;
    const int tx   = tid & 15;
    const int ty   = tid >> 4;
    const int lrow = tid >> 2;
    const int lcol = (tid & 3) << 2;

    ull acc[8][4];
#pragma unroll
    for (int i = 0; i < 8; i++)
#pragma unroll
        for (int j = 0; j < 4; j++) acc[i][j] = 0ull;

    const float* Aptr = A + (size_t)(bm + lrow) * lda + lcol;
    const float* Bptr = B + (size_t)(bn + lrow) * ldb + lcol;

    {
        float4 a0 = *(const float4*)Aptr;
        float4 a1 = *(const float4*)(Aptr + (size_t)64 * lda);
        float4 b0 = *(const float4*)Bptr;
        float4 b1 = *(const float4*)(Bptr + (size_t)64 * ldb);
        As[0][lcol+0][lrow]    = a0.x; As[0][lcol+1][lrow]    = a0.y;
        As[0][lcol+2][lrow]    = a0.z; As[0][lcol+3][lrow]    = a0.w;
        As[0][lcol+0][lrow+64] = a1.x; As[0][lcol+1][lrow+64] = a1.y;
        As[0][lcol+2][lrow+64] = a1.z; As[0][lcol+3][lrow+64] = a1.w;
        Bs[0][lcol+0][lrow]    = b0.x; Bs[0][lcol+1][lrow]    = b0.y;
        Bs[0][lcol+2][lrow]    = b0.z; Bs[0][lcol+3][lrow]    = b0.w;
        Bs[0][lcol+0][lrow+64] = b1.x; Bs[0][lcol+1][lrow+64] = b1.y;
        Bs[0][lcol+2][lrow+64] = b1.z; Bs[0][lcol+3][lrow+64] = b1.w;
    }
    __syncthreads();

    const int ntile = K >> 4;
    int buf = 0;
    for (int t = 0; t < ntile; t++) {
        float4 a0n, a1n, b0n, b1n;
        if (t + 1 < ntile) {
            const float* Ap = Aptr + (t + 1) * 16;
            const float* Bp = Bptr + (t + 1) * 16;
            a0n = *(const float4*)Ap;
            a1n = *(const float4*)(Ap + (size_t)64 * lda);
            b0n = *(const float4*)Bp;
            b1n = *(const float4*)(Bp + (size_t)64 * ldb);
        }
#pragma unroll
        for (int k = 0; k < 16; k++) {
            float4 av0 = *(const float4*)&As[buf][k][ty << 2];
            float4 av1 = *(const float4*)&As[buf][k][(ty << 2) + 64];
            const ull* bp0 = (const ull*)&Bs[buf][k][tx << 2];
            const ull* bp1 = (const ull*)&Bs[buf][k][(tx << 2) + 64];
            ull b01 = bp0[0], b23 = bp0[1];
            ull b45 = bp1[0], b67 = bp1[1];
            float a[8] = {av0.x, av0.y, av0.z, av0.w,
                          av1.x, av1.y, av1.z, av1.w};
#pragma unroll
            for (int i = 0; i < 8; i++) {
                ull ap = pack2(a[i], a[i]);
                ffma2(acc[i][0], ap, b01);
                ffma2(acc[i][1], ap, b23);
                ffma2(acc[i][2], ap, b45);
                ffma2(acc[i][3], ap, b67);
            }
        }
        if (t + 1 < ntile) {
            int nb = buf ^ 1;
            As[nb][lcol+0][lrow]    = a0n.x; As[nb][lcol+1][lrow]    = a0n.y;
            As[nb][lcol+2][lrow]    = a0n.z; As[nb][lcol+3][lrow]    = a0n.w;
            As[nb][lcol+0][lrow+64] = a1n.x; As[nb][lcol+1][lrow+64] = a1n.y;
            As[nb][lcol+2][lrow+64] = a1n.z; As[nb][lcol+3][lrow+64] = a1n.w;
            Bs[nb][lcol+0][lrow]    = b0n.x; Bs[nb][lcol+1][lrow]    = b0n.y;
            Bs[nb][lcol+2][lrow]    = b0n.z; Bs[nb][lcol+3][lrow]    = b0n.w;
            Bs[nb][lcol+0][lrow+64] = b1n.x; Bs[nb][lcol+1][lrow+64] = b1n.y;
            Bs[nb][lcol+2][lrow+64] = b1n.z; Bs[nb][lcol+3][lrow+64] = b1n.w;
            __syncthreads();
            buf = nb;
        }
    }

    float bv[8];
#pragma unroll
    for (int j = 0; j < 8; j++) {
        int col = (j < 4) ? (tx << 2) + j : 64 + (tx << 2) + (j - 4);
        bv[j] = bias[bn + col];
    }
#pragma unroll
    for (int i = 0; i < 8; i++) {
        int row = bm + ((i < 4) ? (ty << 2) + i : 64 + (ty << 2) + (i - 4));
#pragma unroll
        for (int j2 = 0; j2 < 4; j2++) {
            float v0, v1;
            unpack2(acc[i][j2], v0, v1);
            int j = j2 * 2;
            int col0 = bn + ((j < 4) ? (tx << 2) + j : 64 + (tx << 2) + (j - 4));
            v0 += bv[j];
            v1 += bv[j + 1];
            if (MODE == 0) {
                size_t o = (size_t)row * 256 + col0;
                if (z == 0) {
                    split_bf16(v0, g_qh[o], g_ql[o]);
                    split_bf16(v1, g_qh[o + 1], g_ql[o + 1]);
                } else if (z == 1) {
                    split_bf16(v0, g_kh[o], g_kl[o]);
                    split_bf16(v1, g_kh[o + 1], g_kl[o + 1]);
                } else {
                    g_gx[o]     = v0;
                    g_gx[o + 1] = v1;
                }
            } else {
                int n = row / NUMB, t = row - n * NUMB;
                v0 += ori[(size_t)(n * 512 + col0) * NUMB + t];
                v1 += ori[(size_t)(n * 512 + col0 + 1) * NUMB + t];
                *(float2*)&Cout[(size_t)row * ldc + col0] = make_float2(v0, v1);
            }
        }
    }
}

// ---------------------------------------------------------------------------
// Transpose gx (T,256) -> Gt hi/lo (256, T) bf16
// ---------------------------------------------------------------------------
__global__ void __launch_bounds__(256)
transpose_g_kernel()
{
    __shared__ float s[32][33];
    const int r0 = blockIdx.x * 32;
    const int c0 = blockIdx.y * 32;
    const int tx = threadIdx.x & 31;
    const int ty = threadIdx.x >> 5;
#pragma unroll
    for (int i = 0; i < 4; i++) {
        int r = ty + i * 8;
        s[r][tx] = g_gx[(size_t)(r0 + r) * 256 + c0 + tx];
    }
    __syncthreads();
#pragma unroll
    for (int i = 0; i < 4; i++) {
        int c = ty + i * 8;
        float x = s[tx][c];
        __nv_bfloat16 h, l;
        split_bf16(x, h, l);
        size_t o = (size_t)(c0 + c) * T_TOK + r0 + tx;
        g_gth[o] = h;
        g_gtl[o] = l;
    }
}

// ---------------------------------------------------------------------------
// HMMA (mma.sync bf16) 3-term-split NT GEMM: D[M,N] = A@B^T, fp32 accum.
// CTA tile BM x 128, 8 warps (2 M-groups x 4 N-groups), warp tile (BM/2) x 32.
// K consumed in chunks of 64 bf16 (128B rows, SW128 swizzle, cp.async dbl buf).
// MASK: block-diagonal -1000 epilogue.
// ---------------------------------------------------------------------------
template<int BM, bool MASK>
__global__ void __launch_bounds__(256)
hmma_gemm(const __nv_bfloat16* __restrict__ Ah_, const __nv_bfloat16* __restrict__ Al_,
          const __nv_bfloat16* __restrict__ Bh_, const __nv_bfloat16* __restrict__ Bl_,
          float* __restrict__ C, int ldc, int K)
{
    constexpr int MF    = BM / 32;            // M fragments per warp
    constexpr int ASZ   = BM * 128;           // bytes per A tile
    constexpr int STAGE = 2 * ASZ + 32768;    // Ah,Al + Bh,Bl(16KB each)

    extern __shared__ char dsm[];
    const uint32_t sb = (smem_u32(dsm) + 1023u) & ~1023u;

    const int tid  = threadIdx.x;
    const int lane = tid & 31;
    const int wid  = tid >> 5;
    const int wm   = wid >> 2;                // 0..1
    const int wn   = wid & 3;                 // 0..3
    const int bm   = blockIdx.y * BM;
    const int bn   = blockIdx.x * 128;

    const size_t ldb = (size_t)K * 2;         // bytes per row (all operands)
    const char* srcAh = (const char*)Ah_ + (size_t)bm * ldb;
    const char* srcAl = (const char*)Al_ + (size_t)bm * ldb;
    const char* srcBh = (const char*)Bh_ + (size_t)bn * ldb;
    const char* srcBl = (const char*)Bl_ + (size_t)bn * ldb;

    const int NC = K >> 6;

    auto load_stage = [&](int st, int c) {
        uint32_t base = sb + (uint32_t)st * STAGE;
        size_t gof = (size_t)c * 128;
#pragma unroll
        for (int idx = tid; idx < BM * 8; idx += 256) {
            int r = idx >> 3, c16 = (idx & 7) << 4;
            uint32_t sw = SWZ((uint32_t)(r * 128 + c16));
            size_t go = (size_t)r * ldb + c16 + gof;
            cp16(base + sw,       srcAh + go);
            cp16(base + ASZ + sw, srcAl + go);
        }
#pragma unroll
        for (int idx = tid; idx < 128 * 8; idx += 256) {
            int r = idx >> 3, c16 = (idx & 7) << 4;
            uint32_t sw = SWZ((uint32_t)(r * 128 + c16));
            size_t go = (size_t)r * ldb + c16 + gof;
            cp16(base + 2 * ASZ + sw,         srcBh + go);
            cp16(base + 2 * ASZ + 16384 + sw, srcBl + go);
        }
        cp_commit();
    };

    // per-lane fragment address components
    uint32_t aBase[MF], aXor[MF];
#pragma unroll
    for (int mf = 0; mf < MF; mf++) {
        int row = wm * (BM / 2) + mf * 16 + (lane & 15);
        aBase[mf] = (uint32_t)(row * 128);
        aXor[mf]  = (uint32_t)((row & 7) << 4);
    }
    const uint32_t akp = (uint32_t)((lane >> 4) * 16);
    uint32_t bBase[2], bXor[2];
#pragma unroll
    for (int np = 0; np < 2; np++) {
        int row = wn * 32 + np * 16 + (lane & 7) + ((lane >> 4) & 1) * 8;
        bBase[np] = (uint32_t)(row * 128);
        bXor[np]  = (uint32_t)((row & 7) << 4);
    }
    const uint32_t bkp = (uint32_t)(((lane >> 3) & 1) * 16);

    float acc[MF][4][4];
#pragma unroll
    for (int i = 0; i < MF; i++)
#pragma unroll
        for (int j = 0; j < 4; j++)
#pragma unroll
            for (int k = 0; k < 4; k++) acc[i][j][k] = 0.f;

    load_stage(0, 0);

    for (int c = 0; c < NC; c++) {
        int buf = c & 1;
        if (c + 1 < NC) {
            load_stage(buf ^ 1, c + 1);
            asm volatile("cp.async.wait_group 1;" ::: "memory");
        } else {
            asm volatile("cp.async.wait_group 0;" ::: "memory");
        }
        __syncthreads();

        const uint32_t tA  = sb + (uint32_t)buf * STAGE;
        const uint32_t tAl = tA + ASZ;
        const uint32_t tBh = tA + 2 * ASZ;
        const uint32_t tBl = tBh + 16384;

#pragma unroll
        for (int kk = 0; kk < 4; kk++) {
            uint32_t ah[MF][4], al[MF][4], bh[2][4], bl[2][4];
#pragma unroll
            for (int mf = 0; mf < MF; mf++) {
                uint32_t off = aBase[mf] + ((kk * 32 + akp) ^ aXor[mf]);
                ldsm4(ah[mf], tA  + off);
                ldsm4(al[mf], tAl + off);
            }
#pragma unroll
            for (int np = 0; np < 2; np++) {
                uint32_t off = bBase[np] + ((kk * 32 + bkp) ^ bXor[np]);
                ldsm4(bh[np], tBh + off);
                ldsm4(bl[np], tBl + off);
            }
#pragma unroll
            for (int mf = 0; mf < MF; mf++)
#pragma unroll
                for (int nf = 0; nf < 4; nf++)
                    mma16816(acc[mf][nf], ah[mf], &bh[nf >> 1][(nf & 1) * 2]);
#pragma unroll
            for (int mf = 0; mf < MF; mf++)
#pragma unroll
                for (int nf = 0; nf < 4; nf++)
                    mma16816(acc[mf][nf], al[mf], &bh[nf >> 1][(nf & 1) * 2]);
#pragma unroll
            for (int mf = 0; mf < MF; mf++)
#pragma unroll
                for (int nf = 0; nf < 4; nf++)
                    mma16816(acc[mf][nf], ah[mf], &bl[nf >> 1][(nf & 1) * 2]);
        }
        __syncthreads();
    }

    // epilogue
#pragma unroll
    for (int mf = 0; mf < MF; mf++) {
        int row0 = bm + wm * (BM / 2) + mf * 16 + (lane >> 2);
#pragma unroll
        for (int nf = 0; nf < 4; nf++) {
            int col0 = bn + wn * 32 + nf * 8 + ((lane & 3) << 1);
            float v0 = acc[mf][nf][0], v1 = acc[mf][nf][1];
            float v2 = acc[mf][nf][2], v3 = acc[mf][nf][3];
            if (MASK) {
                int cb0 = col0 / NUMB, cb1 = (col0 + 1) / NUMB;
                int rb0 = row0 / NUMB, rb1 = (row0 + 8) / NUMB;
                if (rb0 == cb0) v0 = -1000.0f;
                if (rb0 == cb1) v1 = -1000.0f;
                if (rb1 == cb0) v2 = -1000.0f;
                if (rb1 == cb1) v3 = -1000.0f;
            }
            *(float2*)&C[(size_t)row0 * ldc + col0]       = make_float2(v0, v1);
            *(float2*)&C[(size_t)(row0 + 8) * ldc + col0] = make_float2(v2, v3);
        }
    }
}

// ---------------------------------------------------------------------------
// Row softmax in place + emit bf16 hi/lo copies of P for the AV MMA.
// ---------------------------------------------------------------------------
__global__ void __launch_bounds__(256)
softmax_kernel(float* __restrict__ attn)
{
    const int row = blockIdx.x;
    float* p = attn + (size_t)row * T_TOK;
    __nv_bfloat16* ph = g_ph + (size_t)row * T_TOK;
    __nv_bfloat16* pl = g_pl + (size_t)row * T_TOK;
    const int tid = threadIdx.x;
    const unsigned FULL = 0xffffffffu;
    __shared__ float red[8];

    float v[23];
    float mx = -1e30f;
#pragma unroll
    for (int i = 0; i < 23; i++) {
        v[i] = p[tid + (i << 8)];
        mx = fmaxf(mx, v[i]);
    }
#pragma unroll
    for (int o = 16; o; o >>= 1) mx = fmaxf(mx, __shfl_xor_sync(FULL, mx, o));
    if ((tid & 31) == 0) red[tid >> 5] = mx;
    __syncthreads();
    if (tid < 32) {
        float m2 = (tid < 8) ? red[tid] : -1e30f;
#pragma unroll
        for (int o = 4; o; o >>= 1) m2 = fmaxf(m2, __shfl_xor_sync(FULL, m2, o));
        if (tid == 0) red[0] = m2;
    }
    __syncthreads();
    mx = red[0];
    __syncthreads();

    float s = 0.f;
#pragma unroll
    for (int i = 0; i < 23; i++) {
        v[i] = __expf(v[i] - mx);
        s += v[i];
    }
#pragma unroll
    for (int o = 16; o; o >>= 1) s += __shfl_xor_sync(FULL, s, o);
    if ((tid & 31) == 0) red[tid >> 5] = s;
    __syncthreads();
    if (tid < 32) {
        float s2 = (tid < 8) ? red[tid] : 0.f;
#pragma unroll
        for (int o = 4; o; o >>= 1) s2 += __shfl_xor_sync(FULL, s2, o);
        if (tid == 0) red[0] = s2;
    }
    __syncthreads();
    float inv = 1.f / red[0];
#pragma unroll
    for (int i = 0; i < 23; i++) {
        int idx = tid + (i << 8);
        float r = v[i] * inv;
        p[idx] = r;
        __nv_bfloat16 h, l;
        split_bf16(r, h, l);
        ph[idx] = h;
        pl[idx] = l;
    }
}

// ---------------------------------------------------------------------------
extern "C" void kernel_launch(void* const* d_in, const int* in_sizes, int n_in,
                              void* d_out, int out_size)
{
    const float* ori     = (const float*)d_in[0];
    const float* gamma   = (const float*)d_in[1];
    const float* beta    = (const float*)d_in[2];
    const float* mean    = (const float*)d_in[3];
    const float* var     = (const float*)d_in[4];
    const float* theta_w = (const float*)d_in[5];
    const float* theta_b = (const float*)d_in[6];
    const float* phi_w   = (const float*)d_in[7];
    const float* phi_b   = (const float*)d_in[8];
    const float* g_w     = (const float*)d_in[9];
    const float* g_b     = (const float*)d_in[10];
    const float* W_w     = (const float*)d_in[11];
    const float* W_b     = (const float*)d_in[12];

    float* att_fea = (float*)d_out;                                  // (128,46,512)
    float* fdiv    = (float*)d_out + (size_t)NB * NUMB * 512;        // (5888,5888)

    float *feat, *y;
    __nv_bfloat16 *qh, *ql, *kh, *kl, *gth, *gtl, *ph, *pl;
    cudaGetSymbolAddress((void**)&feat, g_feat);
    cudaGetSymbolAddress((void**)&y,    g_y);
    cudaGetSymbolAddress((void**)&qh,   g_qh);
    cudaGetSymbolAddress((void**)&ql,   g_ql);
    cudaGetSymbolAddress((void**)&kh,   g_kh);
    cudaGetSymbolAddress((void**)&kl,   g_kl);
    cudaGetSymbolAddress((void**)&gth,  g_gth);
    cudaGetSymbolAddress((void**)&gtl,  g_gtl);
    cudaGetSymbolAddress((void**)&ph,   g_ph);
    cudaGetSymbolAddress((void**)&pl,   g_pl);

    // dynamic smem sizes: 2 stages * (2*A + 32KB B) + 1KB align slack
    const int SM_ATTN = 2 * (2 * 128 * 128 + 32768) + 1024;   // 132 KB
    const int SM_AV   = 2 * (2 *  64 * 128 + 32768) + 1024;   //  99 KB
    cudaFuncSetAttribute(hmma_gemm<128, true>,
                         cudaFuncAttributeMaxDynamicSharedMemorySize, SM_ATTN);
    cudaFuncSetAttribute(hmma_gemm<64, false>,
                         cudaFuncAttributeMaxDynamicSharedMemorySize, SM_AV);

    // 1) BN + ReLU + transpose -> feat (T, 512)
    bn_relu_kernel<<<dim3(16, NB), 256>>>(ori, gamma, beta, mean, var);

    // 2) Projections (FFMA2) -> qh/ql, kh/kl bf16 pairs; gx fp32
    gemm_nt<0><<<dim3(2, 46, 3), 256>>>(feat,
                                        theta_w, phi_w, g_w,
                                        theta_b, phi_b, g_b,
                                        nullptr, 512, 512, 0, 512, nullptr);

    // 3) Gt hi/lo (256, T) transpose of gx
    transpose_g_kernel<<<dim3(184, 8), 256>>>();

    // 4) attn = xt @ xp^T (HMMA 3-term split) + mask -> fdiv logits
    hmma_gemm<128, true><<<dim3(46, 46), 256, SM_ATTN>>>(qh, ql, kh, kl,
                                                         fdiv, T_TOK, 256);

    // 5) softmax rows in place; emit P hi/lo
    softmax_kernel<<<T_TOK, 256>>>(fdiv);

    // 6) y = P @ g_x via HMMA: A = P hi/lo (T,T), B = Gt hi/lo (256,T)
    hmma_gemm<64, false><<<dim3(2, 92), 256, SM_AV>>>(ph, pl, gth, gtl,
                                                      y, 256, T_TOK);

    // 7) att_fea = y @ W_w^T + W_b + ori^T  (FFMA2)
    gemm_nt<2><<<dim3(4, 46), 256>>>(y, W_w, nullptr, nullptr,
                                     W_b, nullptr, nullptr,
                                     att_fea, 256, 256, 512, 256, ori);
}

// round 8
// speedup vs baseline: 3.3469x; 1.1490x over previous
#include <cuda_runtime.h>
#include <cuda_bf16.h>
#include <cstdint>

#define T_TOK 5888
#define NUMB  46
#define NB    128

typedef __nv_bfloat16 bf16;

// ---------------------------------------------------------------------------
// Scratch (__device__ globals; no allocation allowed)
// ---------------------------------------------------------------------------
__device__ bf16 g_fh[T_TOK * 512];          // feat hi (T, 512)
__device__ bf16 g_fl[T_TOK * 512];          // feat lo
__device__ bf16 g_pwh[3 * 256 * 512];       // [theta|phi|g] weight hi (z,256,512)
__device__ bf16 g_pwl[3 * 256 * 512];       // weight lo
__device__ bf16 g_fwh[512 * 256];           // W_w hi
__device__ bf16 g_fwl[512 * 256];           // W_w lo
__device__ float g_bias[768];               // [theta_b|phi_b|g_b]
__device__ float g_gx[T_TOK * 256];         // gx fp32 (pre-transpose)
__device__ bf16 g_qh[T_TOK * 256];          // x_theta hi/lo
__device__ bf16 g_ql[T_TOK * 256];
__device__ bf16 g_kh[T_TOK * 256];          // x_phi hi/lo
__device__ bf16 g_kl[T_TOK * 256];
__device__ bf16 g_gth[256 * T_TOK];         // g_x^T hi/lo (256, T)
__device__ bf16 g_gtl[256 * T_TOK];
__device__ bf16 g_yh[T_TOK * 256];          // y hi/lo
__device__ bf16 g_yl[T_TOK * 256];
__device__ bf16 g_ph[34668544];             // P hi (T, T)
__device__ bf16 g_pl[34668544];             // P lo (T, T)

// ---------------------------------------------------------------------------
// PTX helpers (baseline PTX only)
// ---------------------------------------------------------------------------
__device__ __forceinline__ uint32_t smem_u32(const void* p) {
    uint32_t a;
    asm("{ .reg .u64 t; cvta.to.shared.u64 t, %1; cvt.u32.u64 %0, t; }"
        : "=r"(a) : "l"(p));
    return a;
}
__device__ __forceinline__ void cp16(uint32_t s, const void* g) {
    asm volatile("cp.async.cg.shared.global [%0], [%1], 16;" :: "r"(s), "l"(g) : "memory");
}
__device__ __forceinline__ void cp_commit() {
    asm volatile("cp.async.commit_group;" ::: "memory");
}
template<int N>
__device__ __forceinline__ void cp_wait() {
    asm volatile("cp.async.wait_group %0;" :: "n"(N) : "memory");
}
__device__ __forceinline__ void ldsm4(uint32_t* r, uint32_t addr) {
    asm volatile("ldmatrix.sync.aligned.m8n8.x4.shared.b16 {%0,%1,%2,%3},[%4];"
                 : "=r"(r[0]), "=r"(r[1]), "=r"(r[2]), "=r"(r[3]) : "r"(addr));
}
__device__ __forceinline__ void mma16816(float* c, const uint32_t* a, const uint32_t* b) {
    asm volatile("mma.sync.aligned.m16n8k16.row.col.f32.bf16.bf16.f32 "
                 "{%0,%1,%2,%3},{%4,%5,%6,%7},{%8,%9},{%0,%1,%2,%3};"
                 : "+f"(c[0]), "+f"(c[1]), "+f"(c[2]), "+f"(c[3])
                 : "r"(a[0]), "r"(a[1]), "r"(a[2]), "r"(a[3]),
                   "r"(b[0]), "r"(b[1]));
}
#define SWZ(x) ((x) ^ (((x) >> 3) & 0x70))

__device__ __forceinline__ void split_bf16(float x, bf16& h, bf16& l) {
    h = __float2bfloat16_rn(x);
    l = __float2bfloat16_rn(x - __bfloat162float(h));
}
__device__ __forceinline__ void store_split2(bf16* H, bf16* L, size_t o,
                                             float v0, float v1) {
    __nv_bfloat162 h2, l2;
    split_bf16(v0, h2.x, l2.x);
    split_bf16(v1, h2.y, l2.y);
    *(__nv_bfloat162*)&H[o] = h2;
    *(__nv_bfloat162*)&L[o] = l2;
}

// ---------------------------------------------------------------------------
// BN(inference)+ReLU+transpose: ori (N,C,46) -> feat hi/lo (T, C) bf16
// ---------------------------------------------------------------------------
__global__ void __launch_bounds__(256)
bn_relu_kernel(const float* __restrict__ ori,
               const float* __restrict__ gamma,
               const float* __restrict__ beta,
               const float* __restrict__ mean,
               const float* __restrict__ var)
{
    __shared__ float s[32][47];
    const int n  = blockIdx.y;
    const int c0 = blockIdx.x * 32;
    const int tid = threadIdx.x;

    for (int i = tid; i < 32 * NUMB; i += 256) {
        int c = i / NUMB;
        int t = i - c * NUMB;
        int cc = c0 + c;
        float inv = gamma[cc] * rsqrtf(var[cc] + 1e-5f);
        float b   = beta[cc] - mean[cc] * inv;
        float v   = ori[(size_t)(n * 512 + cc) * NUMB + t] * inv + b;
        s[c][t] = fmaxf(v, 0.f);
    }
    __syncthreads();
    for (int i = tid; i < 32 * NUMB; i += 256) {
        int t = i >> 5;
        int c = i & 31;
        size_t o = (size_t)(n * NUMB + t) * 512 + c0 + c;
        split_bf16(s[c][t], g_fh[o], g_fl[o]);
    }
}

// ---------------------------------------------------------------------------
// Prep: split weights to bf16 hi/lo, gather biases
// ---------------------------------------------------------------------------
__global__ void __launch_bounds__(256)
prep_weights(const float* __restrict__ tw, const float* __restrict__ pw,
             const float* __restrict__ gw, const float* __restrict__ ww,
             const float* __restrict__ tb, const float* __restrict__ pb,
             const float* __restrict__ gb)
{
    int i = blockIdx.x * 256 + threadIdx.x;
    if (i < 393216) {
        int z = i / 131072;
        int j = i - z * 131072;
        const float* w = (z == 0) ? tw : (z == 1) ? pw : gw;
        split_bf16(w[j], g_pwh[i], g_pwl[i]);
    } else if (i < 524288) {
        int j = i - 393216;
        split_bf16(ww[j], g_fwh[j], g_fwl[j]);
    }
    if (i < 768) {
        float b = (i < 256) ? tb[i] : (i < 512) ? pb[i - 256] : gb[i - 512];
        g_bias[i] = b;
    }
}

// ---------------------------------------------------------------------------
// Transpose gx (T,256) -> Gt hi/lo (256, T) bf16
// ---------------------------------------------------------------------------
__global__ void __launch_bounds__(256)
transpose_g_kernel()
{
    __shared__ float s[32][33];
    const int r0 = blockIdx.x * 32;
    const int c0 = blockIdx.y * 32;
    const int tx = threadIdx.x & 31;
    const int ty = threadIdx.x >> 5;
#pragma unroll
    for (int i = 0; i < 4; i++) {
        int r = ty + i * 8;
        s[r][tx] = g_gx[(size_t)(r0 + r) * 256 + c0 + tx];
    }
    __syncthreads();
#pragma unroll
    for (int i = 0; i < 4; i++) {
        int c = ty + i * 8;
        size_t o = (size_t)(c0 + c) * T_TOK + r0 + tx;
        split_bf16(s[tx][c], g_gth[o], g_gtl[o]);
    }
}

// ---------------------------------------------------------------------------
// HMMA (mma.sync bf16) 3-term-split NT GEMM: D[M,N] = A@B^T, fp32 accum.
// CTA tile BM x 128, 8 warps (2x4), S-stage cp.async pipeline, SW128 smem.
// EPI 0: attn (mask, fp32 out)     EPI 1: projections (bias; z-select output)
// EPI 2: AV (emit y hi/lo)         EPI 3: final (bias + residual, fp32 out)
// ---------------------------------------------------------------------------
template<int BM, int S, int EPI>
__global__ void __launch_bounds__(256)
hmma_gemm(const bf16* __restrict__ Ah_, const bf16* __restrict__ Al_,
          const bf16* __restrict__ Bh_, const bf16* __restrict__ Bl_,
          float* __restrict__ C, int ldc, int K,
          const float* __restrict__ bias, const float* __restrict__ ori)
{
    constexpr int MF    = BM / 32;
    constexpr int ASZ   = BM * 128;
    constexpr int STAGE = 2 * ASZ + 32768;

    extern __shared__ char dsm[];
    const uint32_t sb = (smem_u32(dsm) + 1023u) & ~1023u;

    const int tid  = threadIdx.x;
    const int lane = tid & 31;
    const int wid  = tid >> 5;
    const int wm   = wid >> 2;
    const int wn   = wid & 3;
    const int bm   = blockIdx.y * BM;
    const int bn   = blockIdx.x * 128;
    const int z    = (EPI == 1) ? blockIdx.z : 0;

    const bf16* Bh = Bh_;
    const bf16* Bl = Bl_;
    if (EPI == 1) { Bh += (size_t)z * 131072; Bl += (size_t)z * 131072; }

    const size_t ldb = (size_t)K * 2;
    const char* srcAh = (const char*)Ah_ + (size_t)bm * ldb;
    const char* srcAl = (const char*)Al_ + (size_t)bm * ldb;
    const char* srcBh = (const char*)Bh  + (size_t)bn * ldb;
    const char* srcBl = (const char*)Bl  + (size_t)bn * ldb;

    const int NC = K >> 6;

    auto load_stage = [&](int st, int c) {
        uint32_t base = sb + (uint32_t)st * STAGE;
        size_t gof = (size_t)c * 128;
#pragma unroll
        for (int idx = tid; idx < BM * 8; idx += 256) {
            int r = idx >> 3, c16 = (idx & 7) << 4;
            uint32_t sw = SWZ((uint32_t)(r * 128 + c16));
            size_t go = (size_t)r * ldb + c16 + gof;
            cp16(base + sw,       srcAh + go);
            cp16(base + ASZ + sw, srcAl + go);
        }
#pragma unroll
        for (int idx = tid; idx < 128 * 8; idx += 256) {
            int r = idx >> 3, c16 = (idx & 7) << 4;
            uint32_t sw = SWZ((uint32_t)(r * 128 + c16));
            size_t go = (size_t)r * ldb + c16 + gof;
            cp16(base + 2 * ASZ + sw,         srcBh + go);
            cp16(base + 2 * ASZ + 16384 + sw, srcBl + go);
        }
        cp_commit();
    };

    uint32_t aBase[MF], aXor[MF];
#pragma unroll
    for (int mf = 0; mf < MF; mf++) {
        int row = wm * (BM / 2) + mf * 16 + (lane & 15);
        aBase[mf] = (uint32_t)(row * 128);
        aXor[mf]  = (uint32_t)((row & 7) << 4);
    }
    const uint32_t akp = (uint32_t)((lane >> 4) * 16);
    uint32_t bBase[2], bXor[2];
#pragma unroll
    for (int np = 0; np < 2; np++) {
        int row = wn * 32 + np * 16 + (lane & 7) + ((lane >> 4) & 1) * 8;
        bBase[np] = (uint32_t)(row * 128);
        bXor[np]  = (uint32_t)((row & 7) << 4);
    }
    const uint32_t bkp = (uint32_t)(((lane >> 3) & 1) * 16);

    float acc[MF][4][4];
#pragma unroll
    for (int i = 0; i < MF; i++)
#pragma unroll
        for (int j = 0; j < 4; j++)
#pragma unroll
            for (int k = 0; k < 4; k++) acc[i][j][k] = 0.f;

    // prologue: stages 0..S-2
#pragma unroll
    for (int s = 0; s < S - 1; s++) load_stage(s, s);

    for (int c = 0; c < NC; c++) {
        int buf = c % S;
        if (c + S - 1 < NC) {
            load_stage((c + S - 1) % S, c + S - 1);
            cp_wait<S - 2>();
        } else {
            cp_wait<0>();
        }
        __syncthreads();

        const uint32_t tA  = sb + (uint32_t)buf * STAGE;
        const uint32_t tAl = tA + ASZ;
        const uint32_t tBh = tA + 2 * ASZ;
        const uint32_t tBl = tBh + 16384;

#pragma unroll
        for (int kk = 0; kk < 4; kk++) {
            uint32_t ah[MF][4], al[MF][4], bh[2][4], bl[2][4];
#pragma unroll
            for (int mf = 0; mf < MF; mf++) {
                uint32_t off = aBase[mf] + ((kk * 32 + akp) ^ aXor[mf]);
                ldsm4(ah[mf], tA  + off);
                ldsm4(al[mf], tAl + off);
            }
#pragma unroll
            for (int np = 0; np < 2; np++) {
                uint32_t off = bBase[np] + ((kk * 32 + bkp) ^ bXor[np]);
                ldsm4(bh[np], tBh + off);
                ldsm4(bl[np], tBl + off);
            }
#pragma unroll
            for (int mf = 0; mf < MF; mf++)
#pragma unroll
                for (int nf = 0; nf < 4; nf++)
                    mma16816(acc[mf][nf], ah[mf], &bh[nf >> 1][(nf & 1) * 2]);
#pragma unroll
            for (int mf = 0; mf < MF; mf++)
#pragma unroll
                for (int nf = 0; nf < 4; nf++)
                    mma16816(acc[mf][nf], al[mf], &bh[nf >> 1][(nf & 1) * 2]);
#pragma unroll
            for (int mf = 0; mf < MF; mf++)
#pragma unroll
                for (int nf = 0; nf < 4; nf++)
                    mma16816(acc[mf][nf], ah[mf], &bl[nf >> 1][(nf & 1) * 2]);
        }
        __syncthreads();
    }

    // ---- epilogue ----
#pragma unroll
    for (int mf = 0; mf < MF; mf++) {
        int rowA = bm + wm * (BM / 2) + mf * 16 + (lane >> 2);
#pragma unroll
        for (int nf = 0; nf < 4; nf++) {
            int col0 = bn + wn * 32 + nf * 8 + ((lane & 3) << 1);
            float v[4] = {acc[mf][nf][0], acc[mf][nf][1],
                          acc[mf][nf][2], acc[mf][nf][3]};
#pragma unroll
            for (int half = 0; half < 2; half++) {
                int row = rowA + half * 8;
                float v0 = v[half * 2], v1 = v[half * 2 + 1];
                if (EPI == 0) {
                    int rb = row / NUMB;
                    if (rb == (col0 + 0) / NUMB) v0 = -1000.0f;
                    if (rb == (col0 + 1) / NUMB) v1 = -1000.0f;
                    *(float2*)&C[(size_t)row * ldc + col0] = make_float2(v0, v1);
                } else if (EPI == 1) {
                    v0 += g_bias[z * 256 + col0];
                    v1 += g_bias[z * 256 + col0 + 1];
                    size_t o = (size_t)row * 256 + col0;
                    if (z == 0)      store_split2(g_qh, g_ql, o, v0, v1);
                    else if (z == 1) store_split2(g_kh, g_kl, o, v0, v1);
                    else             *(float2*)&g_gx[o] = make_float2(v0, v1);
                } else if (EPI == 2) {
                    size_t o = (size_t)row * 256 + col0;
                    store_split2(g_yh, g_yl, o, v0, v1);
                } else {
                    int n = row / NUMB, t = row - n * NUMB;
                    v0 += bias[col0]     + ori[(size_t)(n * 512 + col0) * NUMB + t];
                    v1 += bias[col0 + 1] + ori[(size_t)(n * 512 + col0 + 1) * NUMB + t];
                    *(float2*)&C[(size_t)row * ldc + col0] = make_float2(v0, v1);
                }
            }
        }
    }
}

// ---------------------------------------------------------------------------
// Row softmax in place + emit bf16 hi/lo copies of P for the AV MMA.
// ---------------------------------------------------------------------------
__global__ void __launch_bounds__(256)
softmax_kernel(float* __restrict__ attn)
{
    const int row = blockIdx.x;
    float* p = attn + (size_t)row * T_TOK;
    bf16* ph = g_ph + (size_t)row * T_TOK;
    bf16* pl = g_pl + (size_t)row * T_TOK;
    const int tid = threadIdx.x;
    const unsigned FULL = 0xffffffffu;
    __shared__ float red[8];

    float v[23];
    float mx = -1e30f;
#pragma unroll
    for (int i = 0; i < 23; i++) {
        v[i] = p[tid + (i << 8)];
        mx = fmaxf(mx, v[i]);
    }
#pragma unroll
    for (int o = 16; o; o >>= 1) mx = fmaxf(mx, __shfl_xor_sync(FULL, mx, o));
    if ((tid & 31) == 0) red[tid >> 5] = mx;
    __syncthreads();
    if (tid < 32) {
        float m2 = (tid < 8) ? red[tid] : -1e30f;
#pragma unroll
        for (int o = 4; o; o >>= 1) m2 = fmaxf(m2, __shfl_xor_sync(FULL, m2, o));
        if (tid == 0) red[0] = m2;
    }
    __syncthreads();
    mx = red[0];
    __syncthreads();

    float s = 0.f;
#pragma unroll
    for (int i = 0; i < 23; i++) {
        v[i] = __expf(v[i] - mx);
        s += v[i];
    }
#pragma unroll
    for (int o = 16; o; o >>= 1) s += __shfl_xor_sync(FULL, s, o);
    if ((tid & 31) == 0) red[tid >> 5] = s;
    __syncthreads();
    if (tid < 32) {
        float s2 = (tid < 8) ? red[tid] : 0.f;
#pragma unroll
        for (int o = 4; o; o >>= 1) s2 += __shfl_xor_sync(FULL, s2, o);
        if (tid == 0) red[0] = s2;
    }
    __syncthreads();
    float inv = 1.f / red[0];
#pragma unroll
    for (int i = 0; i < 23; i++) {
        int idx = tid + (i << 8);
        float r = v[i] * inv;
        p[idx] = r;
        split_bf16(r, ph[idx], pl[idx]);
    }
}

// ---------------------------------------------------------------------------
extern "C" void kernel_launch(void* const* d_in, const int* in_sizes, int n_in,
                              void* d_out, int out_size)
{
    const float* ori     = (const float*)d_in[0];
    const float* gamma   = (const float*)d_in[1];
    const float* beta    = (const float*)d_in[2];
    const float* mean    = (const float*)d_in[3];
    const float* var     = (const float*)d_in[4];
    const float* theta_w = (const float*)d_in[5];
    const float* theta_b = (const float*)d_in[6];
    const float* phi_w   = (const float*)d_in[7];
    const float* phi_b   = (const float*)d_in[8];
    const float* g_w     = (const float*)d_in[9];
    const float* g_b     = (const float*)d_in[10];
    const float* W_w     = (const float*)d_in[11];
    const float* W_b     = (const float*)d_in[12];

    float* att_fea = (float*)d_out;                                  // (128,46,512)
    float* fdiv    = (float*)d_out + (size_t)NB * NUMB * 512;        // (5888,5888)

    bf16 *fh, *fl, *pwh, *pwl, *fwh, *fwl;
    bf16 *qh, *ql, *kh, *kl, *gth, *gtl, *yh, *yl, *ph, *pl;
    cudaGetSymbolAddress((void**)&fh,  g_fh);
    cudaGetSymbolAddress((void**)&fl,  g_fl);
    cudaGetSymbolAddress((void**)&pwh, g_pwh);
    cudaGetSymbolAddress((void**)&pwl, g_pwl);
    cudaGetSymbolAddress((void**)&fwh, g_fwh);
    cudaGetSymbolAddress((void**)&fwl, g_fwl);
    cudaGetSymbolAddress((void**)&qh,  g_qh);
    cudaGetSymbolAddress((void**)&ql,  g_ql);
    cudaGetSymbolAddress((void**)&kh,  g_kh);
    cudaGetSymbolAddress((void**)&kl,  g_kl);
    cudaGetSymbolAddress((void**)&gth, g_gth);
    cudaGetSymbolAddress((void**)&gtl, g_gtl);
    cudaGetSymbolAddress((void**)&yh,  g_yh);
    cudaGetSymbolAddress((void**)&yl,  g_yl);
    cudaGetSymbolAddress((void**)&ph,  g_ph);
    cudaGetSymbolAddress((void**)&pl,  g_pl);

    const int SM3 = 3 * 65536 + 1024;                // 197.5 KB (BM=128, S=3)
    const int SM2 = 2 * 49152 + 1024;                // 97 KB   (BM=64,  S=2)
    cudaFuncSetAttribute(hmma_gemm<128, 3, 0>,
                         cudaFuncAttributeMaxDynamicSharedMemorySize, SM3);
    cudaFuncSetAttribute(hmma_gemm<128, 3, 1>,
                         cudaFuncAttributeMaxDynamicSharedMemorySize, SM3);
    cudaFuncSetAttribute(hmma_gemm<64, 2, 2>,
                         cudaFuncAttributeMaxDynamicSharedMemorySize, SM2);
    cudaFuncSetAttribute(hmma_gemm<128, 3, 3>,
                         cudaFuncAttributeMaxDynamicSharedMemorySize, SM3);

    // 1) BN + ReLU + transpose -> feat hi/lo (T, 512)
    bn_relu_kernel<<<dim3(16, NB), 256>>>(ori, gamma, beta, mean, var);

    // 2) Split weights / gather biases
    prep_weights<<<2048, 256>>>(theta_w, phi_w, g_w, W_w, theta_b, phi_b, g_b);

    // 3) Projections (HMMA): z=0 -> qh/ql, z=1 -> kh/kl, z=2 -> gx fp32
    hmma_gemm<128, 3, 1><<<dim3(2, 46, 3), 256, SM3>>>(
        fh, fl, pwh, pwl, nullptr, 0, 512, nullptr, nullptr);

    // 4) Gt hi/lo (256, T) transpose of gx
    transpose_g_kernel<<<dim3(184, 8), 256>>>();

    // 5) attn = xt @ xp^T (HMMA) + mask -> fdiv logits
    hmma_gemm<128, 3, 0><<<dim3(46, 46), 256, SM3>>>(
        qh, ql, kh, kl, fdiv, T_TOK, 256, nullptr, nullptr);

    // 6) softmax rows in place; emit P hi/lo
    softmax_kernel<<<T_TOK, 256>>>(fdiv);

    // 7) y = P @ g_x (HMMA) -> y hi/lo
    hmma_gemm<64, 2, 2><<<dim3(2, 92), 256, SM2>>>(
        ph, pl, gth, gtl, nullptr, 0, T_TOK, nullptr, nullptr);

    // 8) att_fea = y @ W_w^T + W_b + ori^T (HMMA)
    hmma_gemm<128, 3, 3><<<dim3(4, 46), 256, SM3>>>(
        yh, yl, fwh, fwl, att_fea, 512, 256, W_b, ori);
}

// round 9
// speedup vs baseline: 3.8116x; 1.1389x over previous
#include <cuda_runtime.h>
#include <cuda_bf16.h>
#include <cstdint>

#define T_TOK 5888
#define NUMB  46
#define NB    128

typedef __nv_bfloat16 bf16;

// ---------------------------------------------------------------------------
// Scratch (__device__ globals; no allocation allowed)
// ---------------------------------------------------------------------------
__device__ bf16 g_fh[T_TOK * 512];          // feat hi (T, 512)
__device__ bf16 g_fl[T_TOK * 512];          // feat lo
__device__ bf16 g_pwh[3 * 256 * 512];       // [theta|phi|g] weight hi (z,256,512)
__device__ bf16 g_pwl[3 * 256 * 512];       // weight lo
__device__ bf16 g_fwh[512 * 256];           // W_w hi
__device__ bf16 g_fwl[512 * 256];           // W_w lo
__device__ float g_bias[768];               // [theta_b|phi_b|g_b]
__device__ float g_gx[T_TOK * 256];         // gx fp32 (pre-transpose)
__device__ bf16 g_qh[T_TOK * 256];          // x_theta hi/lo
__device__ bf16 g_ql[T_TOK * 256];
__device__ bf16 g_kh[T_TOK * 256];          // x_phi hi/lo
__device__ bf16 g_kl[T_TOK * 256];
__device__ bf16 g_gth[256 * T_TOK];         // g_x^T hi/lo (256, T)
__device__ bf16 g_gtl[256 * T_TOK];
__device__ bf16 g_yh[T_TOK * 256];          // y hi/lo
__device__ bf16 g_yl[T_TOK * 256];
__device__ bf16 g_ph[34668544];             // P hi (T, T) — P quantized bf16

// ---------------------------------------------------------------------------
// PTX helpers (baseline PTX only)
// ---------------------------------------------------------------------------
__device__ __forceinline__ uint32_t smem_u32(const void* p) {
    uint32_t a;
    asm("{ .reg .u64 t; cvta.to.shared.u64 t, %1; cvt.u32.u64 %0, t; }"
        : "=r"(a) : "l"(p));
    return a;
}
__device__ __forceinline__ void cp16(uint32_t s, const void* g) {
    asm volatile("cp.async.cg.shared.global [%0], [%1], 16;" :: "r"(s), "l"(g) : "memory");
}
__device__ __forceinline__ void cp_commit() {
    asm volatile("cp.async.commit_group;" ::: "memory");
}
template<int N>
__device__ __forceinline__ void cp_wait() {
    asm volatile("cp.async.wait_group %0;" :: "n"(N) : "memory");
}
__device__ __forceinline__ void ldsm4(uint32_t* r, uint32_t addr) {
    asm volatile("ldmatrix.sync.aligned.m8n8.x4.shared.b16 {%0,%1,%2,%3},[%4];"
                 : "=r"(r[0]), "=r"(r[1]), "=r"(r[2]), "=r"(r[3]) : "r"(addr));
}
__device__ __forceinline__ void mma16816(float* c, const uint32_t* a, const uint32_t* b) {
    asm volatile("mma.sync.aligned.m16n8k16.row.col.f32.bf16.bf16.f32 "
                 "{%0,%1,%2,%3},{%4,%5,%6,%7},{%8,%9},{%0,%1,%2,%3};"
                 : "+f"(c[0]), "+f"(c[1]), "+f"(c[2]), "+f"(c[3])
                 : "r"(a[0]), "r"(a[1]), "r"(a[2]), "r"(a[3]),
                   "r"(b[0]), "r"(b[1]));
}
#define SWZ(x) ((x) ^ (((x) >> 3) & 0x70))

__device__ __forceinline__ void split_bf16(float x, bf16& h, bf16& l) {
    h = __float2bfloat16_rn(x);
    l = __float2bfloat16_rn(x - __bfloat162float(h));
}
__device__ __forceinline__ void store_split2(bf16* H, bf16* L, size_t o,
                                             float v0, float v1) {
    __nv_bfloat162 h2, l2;
    split_bf16(v0, h2.x, l2.x);
    split_bf16(v1, h2.y, l2.y);
    *(__nv_bfloat162*)&H[o] = h2;
    *(__nv_bfloat162*)&L[o] = l2;
}

// ---------------------------------------------------------------------------
// BN(inference)+ReLU+transpose: ori (N,C,46) -> feat hi/lo (T, C) bf16
// ---------------------------------------------------------------------------
__global__ void __launch_bounds__(256)
bn_relu_kernel(const float* __restrict__ ori,
               const float* __restrict__ gamma,
               const float* __restrict__ beta,
               const float* __restrict__ mean,
               const float* __restrict__ var)
{
    __shared__ float s[32][47];
    const int n  = blockIdx.y;
    const int c0 = blockIdx.x * 32;
    const int tid = threadIdx.x;

    for (int i = tid; i < 32 * NUMB; i += 256) {
        int c = i / NUMB;
        int t = i - c * NUMB;
        int cc = c0 + c;
        float inv = gamma[cc] * rsqrtf(var[cc] + 1e-5f);
        float b   = beta[cc] - mean[cc] * inv;
        float v   = ori[(size_t)(n * 512 + cc) * NUMB + t] * inv + b;
        s[c][t] = fmaxf(v, 0.f);
    }
    __syncthreads();
    for (int i = tid; i < 32 * NUMB; i += 256) {
        int t = i >> 5;
        int c = i & 31;
        size_t o = (size_t)(n * NUMB + t) * 512 + c0 + c;
        split_bf16(s[c][t], g_fh[o], g_fl[o]);
    }
}

// ---------------------------------------------------------------------------
// Prep: split weights to bf16 hi/lo, gather biases
// ---------------------------------------------------------------------------
__global__ void __launch_bounds__(256)
prep_weights(const float* __restrict__ tw, const float* __restrict__ pw,
             const float* __restrict__ gw, const float* __restrict__ ww,
             const float* __restrict__ tb, const float* __restrict__ pb,
             const float* __restrict__ gb)
{
    int i = blockIdx.x * 256 + threadIdx.x;
    if (i < 393216) {
        int z = i / 131072;
        int j = i - z * 131072;
        const float* w = (z == 0) ? tw : (z == 1) ? pw : gw;
        split_bf16(w[j], g_pwh[i], g_pwl[i]);
    } else if (i < 524288) {
        int j = i - 393216;
        split_bf16(ww[j], g_fwh[j], g_fwl[j]);
    }
    if (i < 768) {
        float b = (i < 256) ? tb[i] : (i < 512) ? pb[i - 256] : gb[i - 512];
        g_bias[i] = b;
    }
}

// ---------------------------------------------------------------------------
// Transpose gx (T,256) -> Gt hi/lo (256, T) bf16
// ---------------------------------------------------------------------------
__global__ void __launch_bounds__(256)
transpose_g_kernel()
{
    __shared__ float s[32][33];
    const int r0 = blockIdx.x * 32;
    const int c0 = blockIdx.y * 32;
    const int tx = threadIdx.x & 31;
    const int ty = threadIdx.x >> 5;
#pragma unroll
    for (int i = 0; i < 4; i++) {
        int r = ty + i * 8;
        s[r][tx] = g_gx[(size_t)(r0 + r) * 256 + c0 + tx];
    }
    __syncthreads();
#pragma unroll
    for (int i = 0; i < 4; i++) {
        int c = ty + i * 8;
        size_t o = (size_t)(c0 + c) * T_TOK + r0 + tx;
        split_bf16(s[tx][c], g_gth[o], g_gtl[o]);
    }
}

// ---------------------------------------------------------------------------
// HMMA (mma.sync bf16) split NT GEMM: D[M,N] = A@B^T, fp32 accum.
// CTA tile BM x 128, 8 warps (2x4), S-stage cp.async pipeline, SW128 smem.
// TERMS=3: AhBh + AlBh + AhBl.   TERMS=2: AhBh + AhBl (A hi only in smem).
// EPI 0: attn (mask, fp32 out)     EPI 1: projections (bias; z-select output)
// EPI 2: AV (emit y hi/lo)         EPI 3: final (bias + residual, fp32 out)
// ---------------------------------------------------------------------------
template<int BM, int S, int EPI, int TERMS>
__global__ void __launch_bounds__(256)
hmma_gemm(const bf16* __restrict__ Ah_, const bf16* __restrict__ Al_,
          const bf16* __restrict__ Bh_, const bf16* __restrict__ Bl_,
          float* __restrict__ C, int ldc, int K,
          const float* __restrict__ bias, const float* __restrict__ ori)
{
    constexpr int MF    = BM / 32;
    constexpr int ASZ   = BM * 128;
    constexpr int ANUM  = (TERMS == 3) ? 2 : 1;
    constexpr int STAGE = ANUM * ASZ + 32768;

    extern __shared__ char dsm[];
    const uint32_t sb = (smem_u32(dsm) + 1023u) & ~1023u;

    const int tid  = threadIdx.x;
    const int lane = tid & 31;
    const int wid  = tid >> 5;
    const int wm   = wid >> 2;
    const int wn   = wid & 3;
    const int bm   = blockIdx.y * BM;
    const int bn   = blockIdx.x * 128;
    const int z    = (EPI == 1) ? blockIdx.z : 0;

    const bf16* Bh = Bh_;
    const bf16* Bl = Bl_;
    if (EPI == 1) { Bh += (size_t)z * 131072; Bl += (size_t)z * 131072; }

    const size_t ldb = (size_t)K * 2;
    const char* srcAh = (const char*)Ah_ + (size_t)bm * ldb;
    const char* srcAl = (const char*)Al_ + (size_t)bm * ldb;
    const char* srcBh = (const char*)Bh  + (size_t)bn * ldb;
    const char* srcBl = (const char*)Bl  + (size_t)bn * ldb;

    const int NC = K >> 6;

    auto load_stage = [&](int st, int c) {
        uint32_t base = sb + (uint32_t)st * STAGE;
        size_t gof = (size_t)c * 128;
#pragma unroll
        for (int idx = tid; idx < BM * 8; idx += 256) {
            int r = idx >> 3, c16 = (idx & 7) << 4;
            uint32_t sw = SWZ((uint32_t)(r * 128 + c16));
            size_t go = (size_t)r * ldb + c16 + gof;
            cp16(base + sw, srcAh + go);
            if (TERMS == 3) cp16(base + ASZ + sw, srcAl + go);
        }
#pragma unroll
        for (int idx = tid; idx < 128 * 8; idx += 256) {
            int r = idx >> 3, c16 = (idx & 7) << 4;
            uint32_t sw = SWZ((uint32_t)(r * 128 + c16));
            size_t go = (size_t)r * ldb + c16 + gof;
            cp16(base + ANUM * ASZ + sw,         srcBh + go);
            cp16(base + ANUM * ASZ + 16384 + sw, srcBl + go);
        }
        cp_commit();
    };

    uint32_t aBase[MF], aXor[MF];
#pragma unroll
    for (int mf = 0; mf < MF; mf++) {
        int row = wm * (BM / 2) + mf * 16 + (lane & 15);
        aBase[mf] = (uint32_t)(row * 128);
        aXor[mf]  = (uint32_t)((row & 7) << 4);
    }
    const uint32_t akp = (uint32_t)((lane >> 4) * 16);
    uint32_t bBase[2], bXor[2];
#pragma unroll
    for (int np = 0; np < 2; np++) {
        int row = wn * 32 + np * 16 + (lane & 7) + ((lane >> 4) & 1) * 8;
        bBase[np] = (uint32_t)(row * 128);
        bXor[np]  = (uint32_t)((row & 7) << 4);
    }
    const uint32_t bkp = (uint32_t)(((lane >> 3) & 1) * 16);

    float acc[MF][4][4];
#pragma unroll
    for (int i = 0; i < MF; i++)
#pragma unroll
        for (int j = 0; j < 4; j++)
#pragma unroll
            for (int k = 0; k < 4; k++) acc[i][j][k] = 0.f;

    // prologue: stages 0..S-2
#pragma unroll
    for (int s = 0; s < S - 1; s++) load_stage(s, s);

    for (int c = 0; c < NC; c++) {
        int buf = c % S;
        if (c + S - 1 < NC) {
            load_stage((c + S - 1) % S, c + S - 1);
            cp_wait<S - 2>();
        } else {
            cp_wait<0>();
        }
        __syncthreads();

        const uint32_t tA  = sb + (uint32_t)buf * STAGE;
        const uint32_t tAl = tA + ASZ;
        const uint32_t tBh = tA + ANUM * ASZ;
        const uint32_t tBl = tBh + 16384;

#pragma unroll
        for (int kk = 0; kk < 4; kk++) {
            uint32_t ah[MF][4], al[MF][4], bh[2][4], bl[2][4];
#pragma unroll
            for (int mf = 0; mf < MF; mf++) {
                uint32_t off = aBase[mf] + ((kk * 32 + akp) ^ aXor[mf]);
                ldsm4(ah[mf], tA + off);
                if (TERMS == 3) ldsm4(al[mf], tAl + off);
            }
#pragma unroll
            for (int np = 0; np < 2; np++) {
                uint32_t off = bBase[np] + ((kk * 32 + bkp) ^ bXor[np]);
                ldsm4(bh[np], tBh + off);
                ldsm4(bl[np], tBl + off);
            }
#pragma unroll
            for (int mf = 0; mf < MF; mf++)
#pragma unroll
                for (int nf = 0; nf < 4; nf++)
                    mma16816(acc[mf][nf], ah[mf], &bh[nf >> 1][(nf & 1) * 2]);
            if (TERMS == 3) {
#pragma unroll
                for (int mf = 0; mf < MF; mf++)
#pragma unroll
                    for (int nf = 0; nf < 4; nf++)
                        mma16816(acc[mf][nf], al[mf], &bh[nf >> 1][(nf & 1) * 2]);
            }
#pragma unroll
            for (int mf = 0; mf < MF; mf++)
#pragma unroll
                for (int nf = 0; nf < 4; nf++)
                    mma16816(acc[mf][nf], ah[mf], &bl[nf >> 1][(nf & 1) * 2]);
        }
        __syncthreads();
    }

    // ---- epilogue ----
#pragma unroll
    for (int mf = 0; mf < MF; mf++) {
        int rowA = bm + wm * (BM / 2) + mf * 16 + (lane >> 2);
#pragma unroll
        for (int nf = 0; nf < 4; nf++) {
            int col0 = bn + wn * 32 + nf * 8 + ((lane & 3) << 1);
            float v[4] = {acc[mf][nf][0], acc[mf][nf][1],
                          acc[mf][nf][2], acc[mf][nf][3]};
#pragma unroll
            for (int half = 0; half < 2; half++) {
                int row = rowA + half * 8;
                float v0 = v[half * 2], v1 = v[half * 2 + 1];
                if (EPI == 0) {
                    int rb = row / NUMB;
                    if (rb == (col0 + 0) / NUMB) v0 = -1000.0f;
                    if (rb == (col0 + 1) / NUMB) v1 = -1000.0f;
                    *(float2*)&C[(size_t)row * ldc + col0] = make_float2(v0, v1);
                } else if (EPI == 1) {
                    v0 += g_bias[z * 256 + col0];
                    v1 += g_bias[z * 256 + col0 + 1];
                    size_t o = (size_t)row * 256 + col0;
                    if (z == 0)      store_split2(g_qh, g_ql, o, v0, v1);
                    else if (z == 1) store_split2(g_kh, g_kl, o, v0, v1);
                    else             *(float2*)&g_gx[o] = make_float2(v0, v1);
                } else if (EPI == 2) {
                    size_t o = (size_t)row * 256 + col0;
                    store_split2(g_yh, g_yl, o, v0, v1);
                } else {
                    int n = row / NUMB, t = row - n * NUMB;
                    v0 += bias[col0]     + ori[(size_t)(n * 512 + col0) * NUMB + t];
                    v1 += bias[col0 + 1] + ori[(size_t)(n * 512 + col0 + 1) * NUMB + t];
                    *(float2*)&C[(size_t)row * ldc + col0] = make_float2(v0, v1);
                }
            }
        }
    }
}

// ---------------------------------------------------------------------------
// Row softmax in place + emit bf16 P (hi only) for the AV MMA.
// ---------------------------------------------------------------------------
__global__ void __launch_bounds__(256)
softmax_kernel(float* __restrict__ attn)
{
    const int row = blockIdx.x;
    float* p = attn + (size_t)row * T_TOK;
    bf16* ph = g_ph + (size_t)row * T_TOK;
    const int tid = threadIdx.x;
    const unsigned FULL = 0xffffffffu;
    __shared__ float red[8];

    float v[23];
    float mx = -1e30f;
#pragma unroll
    for (int i = 0; i < 23; i++) {
        v[i] = p[tid + (i << 8)];
        mx = fmaxf(mx, v[i]);
    }
#pragma unroll
    for (int o = 16; o; o >>= 1) mx = fmaxf(mx, __shfl_xor_sync(FULL, mx, o));
    if ((tid & 31) == 0) red[tid >> 5] = mx;
    __syncthreads();
    if (tid < 32) {
        float m2 = (tid < 8) ? red[tid] : -1e30f;
#pragma unroll
        for (int o = 4; o; o >>= 1) m2 = fmaxf(m2, __shfl_xor_sync(FULL, m2, o));
        if (tid == 0) red[0] = m2;
    }
    __syncthreads();
    mx = red[0];
    __syncthreads();

    float s = 0.f;
#pragma unroll
    for (int i = 0; i < 23; i++) {
        v[i] = __expf(v[i] - mx);
        s += v[i];
    }
#pragma unroll
    for (int o = 16; o; o >>= 1) s += __shfl_xor_sync(FULL, s, o);
    if ((tid & 31) == 0) red[tid >> 5] = s;
    __syncthreads();
    if (tid < 32) {
        float s2 = (tid < 8) ? red[tid] : 0.f;
#pragma unroll
        for (int o = 4; o; o >>= 1) s2 += __shfl_xor_sync(FULL, s2, o);
        if (tid == 0) red[0] = s2;
    }
    __syncthreads();
    float inv = 1.f / red[0];
#pragma unroll
    for (int i = 0; i < 23; i++) {
        int idx = tid + (i << 8);
        float r = v[i] * inv;
        p[idx]  = r;
        ph[idx] = __float2bfloat16_rn(r);
    }
}

// ---------------------------------------------------------------------------
extern "C" void kernel_launch(void* const* d_in, const int* in_sizes, int n_in,
                              void* d_out, int out_size)
{
    const float* ori     = (const float*)d_in[0];
    const float* gamma   = (const float*)d_in[1];
    const float* beta    = (const float*)d_in[2];
    const float* mean    = (const float*)d_in[3];
    const float* var     = (const float*)d_in[4];
    const float* theta_w = (const float*)d_in[5];
    const float* theta_b = (const float*)d_in[6];
    const float* phi_w   = (const float*)d_in[7];
    const float* phi_b   = (const float*)d_in[8];
    const float* g_w     = (const float*)d_in[9];
    const float* g_b     = (const float*)d_in[10];
    const float* W_w     = (const float*)d_in[11];
    const float* W_b     = (const float*)d_in[12];

    float* att_fea = (float*)d_out;                                  // (128,46,512)
    float* fdiv    = (float*)d_out + (size_t)NB * NUMB * 512;        // (5888,5888)

    bf16 *fh, *fl, *pwh, *pwl, *fwh, *fwl;
    bf16 *qh, *ql, *kh, *kl, *gth, *gtl, *yh, *yl, *ph;
    cudaGetSymbolAddress((void**)&fh,  g_fh);
    cudaGetSymbolAddress((void**)&fl,  g_fl);
    cudaGetSymbolAddress((void**)&pwh, g_pwh);
    cudaGetSymbolAddress((void**)&pwl, g_pwl);
    cudaGetSymbolAddress((void**)&fwh, g_fwh);
    cudaGetSymbolAddress((void**)&fwl, g_fwl);
    cudaGetSymbolAddress((void**)&qh,  g_qh);
    cudaGetSymbolAddress((void**)&ql,  g_ql);
    cudaGetSymbolAddress((void**)&kh,  g_kh);
    cudaGetSymbolAddress((void**)&kl,  g_kl);
    cudaGetSymbolAddress((void**)&gth, g_gth);
    cudaGetSymbolAddress((void**)&gtl, g_gtl);
    cudaGetSymbolAddress((void**)&yh,  g_yh);
    cudaGetSymbolAddress((void**)&yl,  g_yl);
    cudaGetSymbolAddress((void**)&ph,  g_ph);

    const int SM3  = 3 * 65536 + 1024;               // 197.5 KB (BM=128, S=3, T=3)
    const int SMAV = 2 * (64 * 128 + 32768) + 1024;  // 81 KB   (BM=64,  S=2, T=2)
    cudaFuncSetAttribute(hmma_gemm<128, 3, 0, 3>,
                         cudaFuncAttributeMaxDynamicSharedMemorySize, SM3);
    cudaFuncSetAttribute(hmma_gemm<128, 3, 1, 3>,
                         cudaFuncAttributeMaxDynamicSharedMemorySize, SM3);
    cudaFuncSetAttribute(hmma_gemm<64, 2, 2, 2>,
                         cudaFuncAttributeMaxDynamicSharedMemorySize, SMAV);
    cudaFuncSetAttribute(hmma_gemm<128, 3, 3, 3>,
                         cudaFuncAttributeMaxDynamicSharedMemorySize, SM3);

    // 1) BN + ReLU + transpose -> feat hi/lo (T, 512)
    bn_relu_kernel<<<dim3(16, NB), 256>>>(ori, gamma, beta, mean, var);

    // 2) Split weights / gather biases
    prep_weights<<<2048, 256>>>(theta_w, phi_w, g_w, W_w, theta_b, phi_b, g_b);

    // 3) Projections (HMMA): z=0 -> qh/ql, z=1 -> kh/kl, z=2 -> gx fp32
    hmma_gemm<128, 3, 1, 3><<<dim3(2, 46, 3), 256, SM3>>>(
        fh, fl, pwh, pwl, nullptr, 0, 512, nullptr, nullptr);

    // 4) Gt hi/lo (256, T) transpose of gx
    transpose_g_kernel<<<dim3(184, 8), 256>>>();

    // 5) attn = xt @ xp^T (HMMA, 3-term) + mask -> fdiv logits
    hmma_gemm<128, 3, 0, 3><<<dim3(46, 46), 256, SM3>>>(
        qh, ql, kh, kl, fdiv, T_TOK, 256, nullptr, nullptr);

    // 6) softmax rows in place; emit P bf16 (hi only)
    softmax_kernel<<<T_TOK, 256>>>(fdiv);

    // 7) y = P @ g_x (HMMA, 2-term: Ph·Gh + Ph·Gl) -> y hi/lo
    hmma_gemm<64, 2, 2, 2><<<dim3(2, 92), 256, SMAV>>>(
        ph, ph, gth, gtl, nullptr, 0, T_TOK, nullptr, nullptr);

    // 8) att_fea = y @ W_w^T + W_b + ori^T (HMMA, 3-term)
    hmma_gemm<128, 3, 3, 3><<<dim3(4, 46), 256, SM3>>>(
        yh, yl, fwh, fwl, att_fea, 512, 256, W_b, ori);
}

// round 11
// speedup vs baseline: 3.9118x; 1.0263x over previous
#include <cuda_runtime.h>
#include <cuda_bf16.h>
#include <cuda_fp16.h>
#include <cstdint>

#define T_TOK 5888
#define NUMB  46
#define NB    128

typedef __nv_bfloat16 bf16;

// ---------------------------------------------------------------------------
// Scratch (__device__ globals; no allocation allowed)
// ---------------------------------------------------------------------------
__device__ bf16 g_fh[T_TOK * 512];          // feat hi (T, 512)
__device__ bf16 g_fl[T_TOK * 512];          // feat lo
__device__ bf16 g_pwh[3 * 256 * 512];       // [theta|phi|g] weight hi (z,256,512)
__device__ bf16 g_pwl[3 * 256 * 512];       // weight lo
__device__ bf16 g_fwh[512 * 256];           // W_w hi
__device__ bf16 g_fwl[512 * 256];           // W_w lo
__device__ float g_bias[768];               // [theta_b|phi_b|g_b]
__device__ float g_gx[T_TOK * 256];         // gx fp32 (pre-transpose)
__device__ bf16 g_qh[T_TOK * 256];          // x_theta hi/lo
__device__ bf16 g_ql[T_TOK * 256];
__device__ bf16 g_kh[T_TOK * 256];          // x_phi hi/lo
__device__ bf16 g_kl[T_TOK * 256];
__device__ __half g_gth[256 * T_TOK];       // g_x^T fp16 hi (256, T)
__device__ __half g_gtl[256 * T_TOK];       // g_x^T fp16 lo
__device__ bf16 g_yh[T_TOK * 256];          // y hi/lo (bf16, for final GEMM)
__device__ bf16 g_yl[T_TOK * 256];
__device__ __half g_pf[34668544];           // P fp16 (T, T)

// ---------------------------------------------------------------------------
// PTX helpers (baseline PTX only)
// ---------------------------------------------------------------------------
__device__ __forceinline__ uint32_t smem_u32(const void* p) {
    uint32_t a;
    asm("{ .reg .u64 t; cvta.to.shared.u64 t, %1; cvt.u32.u64 %0, t; }"
        : "=r"(a) : "l"(p));
    return a;
}
__device__ __forceinline__ void cp16(uint32_t s, const void* g) {
    asm volatile("cp.async.cg.shared.global [%0], [%1], 16;" :: "r"(s), "l"(g) : "memory");
}
__device__ __forceinline__ void cp_commit() {
    asm volatile("cp.async.commit_group;" ::: "memory");
}
template<int N>
__device__ __forceinline__ void cp_wait() {
    asm volatile("cp.async.wait_group %0;" :: "n"(N) : "memory");
}
__device__ __forceinline__ void ldsm4(uint32_t* r, uint32_t addr) {
    asm volatile("ldmatrix.sync.aligned.m8n8.x4.shared.b16 {%0,%1,%2,%3},[%4];"
                 : "=r"(r[0]), "=r"(r[1]), "=r"(r[2]), "=r"(r[3]) : "r"(addr));
}
__device__ __forceinline__ void mma16816(float* c, const uint32_t* a, const uint32_t* b) {
    asm volatile("mma.sync.aligned.m16n8k16.row.col.f32.bf16.bf16.f32 "
                 "{%0,%1,%2,%3},{%4,%5,%6,%7},{%8,%9},{%0,%1,%2,%3};"
                 : "+f"(c[0]), "+f"(c[1]), "+f"(c[2]), "+f"(c[3])
                 : "r"(a[0]), "r"(a[1]), "r"(a[2]), "r"(a[3]),
                   "r"(b[0]), "r"(b[1]));
}
__device__ __forceinline__ void mma16816h(float* c, const uint32_t* a, const uint32_t* b) {
    asm volatile("mma.sync.aligned.m16n8k16.row.col.f32.f16.f16.f32 "
                 "{%0,%1,%2,%3},{%4,%5,%6,%7},{%8,%9},{%0,%1,%2,%3};"
                 : "+f"(c[0]), "+f"(c[1]), "+f"(c[2]), "+f"(c[3])
                 : "r"(a[0]), "r"(a[1]), "r"(a[2]), "r"(a[3]),
                   "r"(b[0]), "r"(b[1]));
}
#define SWZ(x) ((x) ^ (((x) >> 3) & 0x70))

__device__ __forceinline__ void split_bf16(float x, bf16& h, bf16& l) {
    h = __float2bfloat16_rn(x);
    l = __float2bfloat16_rn(x - __bfloat162float(h));
}
__device__ __forceinline__ void split_f16(float x, __half& h, __half& l) {
    h = __float2half_rn(x);
    l = __float2half_rn(x - __half2float(h));
}
__device__ __forceinline__ void store_split2(bf16* H, bf16* L, size_t o,
                                             float v0, float v1) {
    __nv_bfloat162 h2, l2;
    split_bf16(v0, h2.x, l2.x);
    split_bf16(v1, h2.y, l2.y);
    *(__nv_bfloat162*)&H[o] = h2;
    *(__nv_bfloat162*)&L[o] = l2;
}

// ---------------------------------------------------------------------------
// BN(inference)+ReLU+transpose: ori (N,C,46) -> feat hi/lo (T, C) bf16
// ---------------------------------------------------------------------------
__global__ void __launch_bounds__(256)
bn_relu_kernel(const float* __restrict__ ori,
               const float* __restrict__ gamma,
               const float* __restrict__ beta,
               const float* __restrict__ mean,
               const float* __restrict__ var)
{
    __shared__ float s[32][47];
    const int n  = blockIdx.y;
    const int c0 = blockIdx.x * 32;
    const int tid = threadIdx.x;

    for (int i = tid; i < 32 * NUMB; i += 256) {
        int c = i / NUMB;
        int t = i - c * NUMB;
        int cc = c0 + c;
        float inv = gamma[cc] * rsqrtf(var[cc] + 1e-5f);
        float b   = beta[cc] - mean[cc] * inv;
        float v   = ori[(size_t)(n * 512 + cc) * NUMB + t] * inv + b;
        s[c][t] = fmaxf(v, 0.f);
    }
    __syncthreads();
    for (int i = tid; i < 32 * NUMB; i += 256) {
        int t = i >> 5;
        int c = i & 31;
        size_t o = (size_t)(n * NUMB + t) * 512 + c0 + c;
        split_bf16(s[c][t], g_fh[o], g_fl[o]);
    }
}

// ---------------------------------------------------------------------------
// Prep: split weights to bf16 hi/lo, gather biases
// ---------------------------------------------------------------------------
__global__ void __launch_bounds__(256)
prep_weights(const float* __restrict__ tw, const float* __restrict__ pw,
             const float* __restrict__ gw, const float* __restrict__ ww,
             const float* __restrict__ tb, const float* __restrict__ pb,
             const float* __restrict__ gb)
{
    int i = blockIdx.x * 256 + threadIdx.x;
    if (i < 393216) {
        int z = i / 131072;
        int j = i - z * 131072;
        const float* w = (z == 0) ? tw : (z == 1) ? pw : gw;
        split_bf16(w[j], g_pwh[i], g_pwl[i]);
    } else if (i < 524288) {
        int j = i - 393216;
        split_bf16(ww[j], g_fwh[j], g_fwl[j]);
    }
    if (i < 768) {
        float b = (i < 256) ? tb[i] : (i < 512) ? pb[i - 256] : gb[i - 512];
        g_bias[i] = b;
    }
}

// ---------------------------------------------------------------------------
// Transpose gx (T,256) -> Gt fp16 hi/lo (256, T)
// ---------------------------------------------------------------------------
__global__ void __launch_bounds__(256)
transpose_g_kernel()
{
    __shared__ float s[32][33];
    const int r0 = blockIdx.x * 32;
    const int c0 = blockIdx.y * 32;
    const int tx = threadIdx.x & 31;
    const int ty = threadIdx.x >> 5;
#pragma unroll
    for (int i = 0; i < 4; i++) {
        int r = ty + i * 8;
        s[r][tx] = g_gx[(size_t)(r0 + r) * 256 + c0 + tx];
    }
    __syncthreads();
#pragma unroll
    for (int i = 0; i < 4; i++) {
        int c = ty + i * 8;
        size_t o = (size_t)(c0 + c) * T_TOK + r0 + tx;
        split_f16(s[tx][c], g_gth[o], g_gtl[o]);
    }
}

// ---------------------------------------------------------------------------
// HMMA (mma.sync) split NT GEMM: D[M,N] = A@B^T, fp32 accum.
// CTA tile BM x 128, 8 warps (2x4), S-stage cp.async pipeline, SW128 smem.
// Loop: wait(chunk c) -> sync -> issue load(c+S-1) -> compute(c).
// The final iteration (and all iterations at S=2) waits ALL groups (tail fix).
// TERMS=3: bf16 AhBh + AlBh + AhBl.   TERMS=2: fp16 A·Bh + A·Bl (A single).
// EPI 0: attn (mask, fp32 out)     EPI 1: projections (bias; z-select output)
// EPI 2: AV (emit y hi/lo bf16)    EPI 3: final (bias + residual, fp32 out)
// ---------------------------------------------------------------------------
template<int BM, int S, int EPI, int TERMS>
__global__ void __launch_bounds__(256)
hmma_gemm(const bf16* __restrict__ Ah_, const bf16* __restrict__ Al_,
          const bf16* __restrict__ Bh_, const bf16* __restrict__ Bl_,
          float* __restrict__ C, int ldc, int K,
          const float* __restrict__ bias, const float* __restrict__ ori)
{
    constexpr int MF    = BM / 32;
    constexpr int ASZ   = BM * 128;
    constexpr int ANUM  = (TERMS == 3) ? 2 : 1;
    constexpr int STAGE = ANUM * ASZ + 2 * 16384;

    extern __shared__ char dsm[];
    const uint32_t sb = (smem_u32(dsm) + 1023u) & ~1023u;

    const int tid  = threadIdx.x;
    const int lane = tid & 31;
    const int wid  = tid >> 5;
    const int wm   = wid >> 2;
    const int wn   = wid & 3;
    const int bm   = blockIdx.y * BM;
    const int bn   = blockIdx.x * 128;
    const int z    = (EPI == 1) ? blockIdx.z : 0;

    const bf16* Bh = Bh_;
    const bf16* Bl = Bl_;
    if (EPI == 1) { Bh += (size_t)z * 131072; Bl += (size_t)z * 131072; }

    const size_t ldb = (size_t)K * 2;
    const char* srcAh = (const char*)Ah_ + (size_t)bm * ldb;
    const char* srcAl = (const char*)Al_ + (size_t)bm * ldb;
    const char* srcBh = (const char*)Bh  + (size_t)bn * ldb;
    const char* srcBl = (const char*)Bl  + (size_t)bn * ldb;

    const int NC = K >> 6;

    auto load_stage = [&](int st, int c) {
        uint32_t base = sb + (uint32_t)st * STAGE;
        size_t gof = (size_t)c * 128;
#pragma unroll
        for (int idx = tid; idx < BM * 8; idx += 256) {
            int r = idx >> 3, c16 = (idx & 7) << 4;
            uint32_t sw = SWZ((uint32_t)(r * 128 + c16));
            size_t go = (size_t)r * ldb + c16 + gof;
            cp16(base + sw, srcAh + go);
            if (TERMS == 3) cp16(base + ASZ + sw, srcAl + go);
        }
#pragma unroll
        for (int idx = tid; idx < 128 * 8; idx += 256) {
            int r = idx >> 3, c16 = (idx & 7) << 4;
            uint32_t sw = SWZ((uint32_t)(r * 128 + c16));
            size_t go = (size_t)r * ldb + c16 + gof;
            cp16(base + ANUM * ASZ + sw,         srcBh + go);
            cp16(base + ANUM * ASZ + 16384 + sw, srcBl + go);
        }
        cp_commit();
    };

    uint32_t aBase[MF], aXor[MF];
#pragma unroll
    for (int mf = 0; mf < MF; mf++) {
        int row = wm * (BM / 2) + mf * 16 + (lane & 15);
        aBase[mf] = (uint32_t)(row * 128);
        aXor[mf]  = (uint32_t)((row & 7) << 4);
    }
    const uint32_t akp = (uint32_t)((lane >> 4) * 16);
    uint32_t bBase[2], bXor[2];
#pragma unroll
    for (int np = 0; np < 2; np++) {
        int row = wn * 32 + np * 16 + (lane & 7) + ((lane >> 4) & 1) * 8;
        bBase[np] = (uint32_t)(row * 128);
        bXor[np]  = (uint32_t)((row & 7) << 4);
    }
    const uint32_t bkp = (uint32_t)(((lane >> 3) & 1) * 16);

    float acc[MF][4][4];
#pragma unroll
    for (int i = 0; i < MF; i++)
#pragma unroll
        for (int j = 0; j < 4; j++)
#pragma unroll
            for (int k = 0; k < 4; k++) acc[i][j][k] = 0.f;

    // prologue: stages 0..S-2
#pragma unroll
    for (int s = 0; s < S - 1; s++) load_stage(s, s);

    for (int c = 0; c < NC; c++) {
        int buf = c % S;
        // wait for chunk c: pending groups = min(S-1, NC-c); need all but
        // the newest S-2 done. Last iteration (or S==2) must drain everything.
        if (S == 2 || c == NC - 1) cp_wait<0>();
        else                       cp_wait<S - 2>();
        __syncthreads();
        // issue next load AFTER the sync (slot was fully read in iter c-1),
        // BEFORE compute (overlaps the whole chunk's MMA work)
        if (c + S - 1 < NC) load_stage((c + S - 1) % S, c + S - 1);

        const uint32_t tA  = sb + (uint32_t)buf * STAGE;
        const uint32_t tAl = tA + ASZ;
        const uint32_t tBh = tA + ANUM * ASZ;
        const uint32_t tBl = tBh + 16384;

#pragma unroll
        for (int kk = 0; kk < 4; kk++) {
            uint32_t ah[MF][4], al[MF][4], bh[2][4], bl[2][4];
#pragma unroll
            for (int mf = 0; mf < MF; mf++) {
                uint32_t off = aBase[mf] + ((kk * 32 + akp) ^ aXor[mf]);
                ldsm4(ah[mf], tA + off);
                if (TERMS == 3) ldsm4(al[mf], tAl + off);
            }
#pragma unroll
            for (int np = 0; np < 2; np++) {
                uint32_t off = bBase[np] + ((kk * 32 + bkp) ^ bXor[np]);
                ldsm4(bh[np], tBh + off);
                ldsm4(bl[np], tBl + off);
            }
            if (TERMS == 2) {
#pragma unroll
                for (int mf = 0; mf < MF; mf++)
#pragma unroll
                    for (int nf = 0; nf < 4; nf++)
                        mma16816h(acc[mf][nf], ah[mf], &bh[nf >> 1][(nf & 1) * 2]);
#pragma unroll
                for (int mf = 0; mf < MF; mf++)
#pragma unroll
                    for (int nf = 0; nf < 4; nf++)
                        mma16816h(acc[mf][nf], ah[mf], &bl[nf >> 1][(nf & 1) * 2]);
            } else {
#pragma unroll
                for (int mf = 0; mf < MF; mf++)
#pragma unroll
                    for (int nf = 0; nf < 4; nf++)
                        mma16816(acc[mf][nf], ah[mf], &bh[nf >> 1][(nf & 1) * 2]);
#pragma unroll
                for (int mf = 0; mf < MF; mf++)
#pragma unroll
                    for (int nf = 0; nf < 4; nf++)
                        mma16816(acc[mf][nf], al[mf], &bh[nf >> 1][(nf & 1) * 2]);
#pragma unroll
                for (int mf = 0; mf < MF; mf++)
#pragma unroll
                    for (int nf = 0; nf < 4; nf++)
                        mma16816(acc[mf][nf], ah[mf], &bl[nf >> 1][(nf & 1) * 2]);
            }
        }
        __syncthreads();
    }

    // ---- epilogue ----
#pragma unroll
    for (int mf = 0; mf < MF; mf++) {
        int rowA = bm + wm * (BM / 2) + mf * 16 + (lane >> 2);
#pragma unroll
        for (int nf = 0; nf < 4; nf++) {
            int col0 = bn + wn * 32 + nf * 8 + ((lane & 3) << 1);
            float v[4] = {acc[mf][nf][0], acc[mf][nf][1],
                          acc[mf][nf][2], acc[mf][nf][3]};
#pragma unroll
            for (int half = 0; half < 2; half++) {
                int row = rowA + half * 8;
                float v0 = v[half * 2], v1 = v[half * 2 + 1];
                if (EPI == 0) {
                    int rb = row / NUMB;
                    if (rb == (col0 + 0) / NUMB) v0 = -1000.0f;
                    if (rb == (col0 + 1) / NUMB) v1 = -1000.0f;
                    *(float2*)&C[(size_t)row * ldc + col0] = make_float2(v0, v1);
                } else if (EPI == 1) {
                    v0 += g_bias[z * 256 + col0];
                    v1 += g_bias[z * 256 + col0 + 1];
                    size_t o = (size_t)row * 256 + col0;
                    if (z == 0)      store_split2(g_qh, g_ql, o, v0, v1);
                    else if (z == 1) store_split2(g_kh, g_kl, o, v0, v1);
                    else             *(float2*)&g_gx[o] = make_float2(v0, v1);
                } else if (EPI == 2) {
                    size_t o = (size_t)row * 256 + col0;
                    store_split2(g_yh, g_yl, o, v0, v1);
                } else {
                    int n = row / NUMB, t = row - n * NUMB;
                    v0 += bias[col0]     + ori[(size_t)(n * 512 + col0) * NUMB + t];
                    v1 += bias[col0 + 1] + ori[(size_t)(n * 512 + col0 + 1) * NUMB + t];
                    *(float2*)&C[(size_t)row * ldc + col0] = make_float2(v0, v1);
                }
            }
        }
    }
}

// ---------------------------------------------------------------------------
// Row softmax in place + emit fp16 P for the AV MMA.
// ---------------------------------------------------------------------------
__global__ void __launch_bounds__(256)
softmax_kernel(float* __restrict__ attn)
{
    const int row = blockIdx.x;
    float* p = attn + (size_t)row * T_TOK;
    __half* pf = g_pf + (size_t)row * T_TOK;
    const int tid = threadIdx.x;
    const unsigned FULL = 0xffffffffu;
    __shared__ float red[8];

    float v[23];
    float mx = -1e30f;
#pragma unroll
    for (int i = 0; i < 23; i++) {
        v[i] = p[tid + (i << 8)];
        mx = fmaxf(mx, v[i]);
    }
#pragma unroll
    for (int o = 16; o; o >>= 1) mx = fmaxf(mx, __shfl_xor_sync(FULL, mx, o));
    if ((tid & 31) == 0) red[tid >> 5] = mx;
    __syncthreads();
    if (tid < 32) {
        float m2 = (tid < 8) ? red[tid] : -1e30f;
#pragma unroll
        for (int o = 4; o; o >>= 1) m2 = fmaxf(m2, __shfl_xor_sync(FULL, m2, o));
        if (tid == 0) red[0] = m2;
    }
    __syncthreads();
    mx = red[0];
    __syncthreads();

    float s = 0.f;
#pragma unroll
    for (int i = 0; i < 23; i++) {
        v[i] = __expf(v[i] - mx);
        s += v[i];
    }
#pragma unroll
    for (int o = 16; o; o >>= 1) s += __shfl_xor_sync(FULL, s, o);
    if ((tid & 31) == 0) red[tid >> 5] = s;
    __syncthreads();
    if (tid < 32) {
        float s2 = (tid < 8) ? red[tid] : 0.f;
#pragma unroll
        for (int o = 4; o; o >>= 1) s2 += __shfl_xor_sync(FULL, s2, o);
        if (tid == 0) red[0] = s2;
    }
    __syncthreads();
    float inv = 1.f / red[0];
#pragma unroll
    for (int i = 0; i < 23; i++) {
        int idx = tid + (i << 8);
        float r = v[i] * inv;
        p[idx]  = r;
        pf[idx] = __float2half_rn(r);
    }
}

// ---------------------------------------------------------------------------
extern "C" void kernel_launch(void* const* d_in, const int* in_sizes, int n_in,
                              void* d_out, int out_size)
{
    const float* ori     = (const float*)d_in[0];
    const float* gamma   = (const float*)d_in[1];
    const float* beta    = (const float*)d_in[2];
    const float* mean    = (const float*)d_in[3];
    const float* var     = (const float*)d_in[4];
    const float* theta_w = (const float*)d_in[5];
    const float* theta_b = (const float*)d_in[6];
    const float* phi_w   = (const float*)d_in[7];
    const float* phi_b   = (const float*)d_in[8];
    const float* g_w     = (const float*)d_in[9];
    const float* g_b     = (const float*)d_in[10];
    const float* W_w     = (const float*)d_in[11];
    const float* W_b     = (const float*)d_in[12];

    float* att_fea = (float*)d_out;                                  // (128,46,512)
    float* fdiv    = (float*)d_out + (size_t)NB * NUMB * 512;        // (5888,5888)

    bf16 *fh, *fl, *pwh, *pwl, *fwh, *fwl;
    bf16 *qh, *ql, *kh, *kl, *yh, *yl;
    __half *gth, *gtl, *pf;
    cudaGetSymbolAddress((void**)&fh,  g_fh);
    cudaGetSymbolAddress((void**)&fl,  g_fl);
    cudaGetSymbolAddress((void**)&pwh, g_pwh);
    cudaGetSymbolAddress((void**)&pwl, g_pwl);
    cudaGetSymbolAddress((void**)&fwh, g_fwh);
    cudaGetSymbolAddress((void**)&fwl, g_fwl);
    cudaGetSymbolAddress((void**)&qh,  g_qh);
    cudaGetSymbolAddress((void**)&ql,  g_ql);
    cudaGetSymbolAddress((void**)&kh,  g_kh);
    cudaGetSymbolAddress((void**)&kl,  g_kl);
    cudaGetSymbolAddress((void**)&gth, g_gth);
    cudaGetSymbolAddress((void**)&gtl, g_gtl);
    cudaGetSymbolAddress((void**)&yh,  g_yh);
    cudaGetSymbolAddress((void**)&yl,  g_yl);
    cudaGetSymbolAddress((void**)&pf,  g_pf);

    const int SM3  = 3 * 65536 + 1024;                 // 197.5 KB (BM=128, S=3, T=3)
    const int SMAV = 2 * (64 * 128 + 32768) + 1024;    // 81 KB   (BM=64,  S=2, T=2)
    cudaFuncSetAttribute(hmma_gemm<128, 3, 0, 3>,
                         cudaFuncAttributeMaxDynamicSharedMemorySize, SM3);
    cudaFuncSetAttribute(hmma_gemm<128, 3, 1, 3>,
                         cudaFuncAttributeMaxDynamicSharedMemorySize, SM3);
    cudaFuncSetAttribute(hmma_gemm<64, 2, 2, 2>,
                         cudaFuncAttributeMaxDynamicSharedMemorySize, SMAV);
    cudaFuncSetAttribute(hmma_gemm<128, 3, 3, 3>,
                         cudaFuncAttributeMaxDynamicSharedMemorySize, SM3);

    // 1) BN + ReLU + transpose -> feat hi/lo (T, 512)
    bn_relu_kernel<<<dim3(16, NB), 256>>>(ori, gamma, beta, mean, var);

    // 2) Split weights / gather biases
    prep_weights<<<2048, 256>>>(theta_w, phi_w, g_w, W_w, theta_b, phi_b, g_b);

    // 3) Projections (HMMA bf16, 3-term): z=0 -> qh/ql, z=1 -> kh/kl, z=2 -> gx
    hmma_gemm<128, 3, 1, 3><<<dim3(2, 46, 3), 256, SM3>>>(
        fh, fl, pwh, pwl, nullptr, 0, 512, nullptr, nullptr);

    // 4) Gt fp16 hi/lo (256, T) transpose of gx
    transpose_g_kernel<<<dim3(184, 8), 256>>>();

    // 5) attn = xt @ xp^T (HMMA bf16, 3-term) + mask -> fdiv logits
    hmma_gemm<128, 3, 0, 3><<<dim3(46, 46), 256, SM3>>>(
        qh, ql, kh, kl, fdiv, T_TOK, 256, nullptr, nullptr);

    // 6) softmax rows in place; emit P fp16
    softmax_kernel<<<T_TOK, 256>>>(fdiv);

    // 7) y = P_f16 @ (Gh + Gl)_f16 (HMMA fp16, 2-term) -> y hi/lo bf16
    hmma_gemm<64, 2, 2, 2><<<dim3(2, 92), 256, SMAV>>>(
        (const bf16*)pf, nullptr, (const bf16*)gth, (const bf16*)gtl,
        nullptr, 0, T_TOK, nullptr, nullptr);

    // 8) att_fea = y @ W_w^T + W_b + ori^T (HMMA bf16, 3-term)
    hmma_gemm<128, 3, 3, 3><<<dim3(4, 46), 256, SM3>>>(
        yh, yl, fwh, fwl, att_fea, 512, 256, W_b, ori);
}